// round 12
// baseline (speedup 1.0000x reference)
#include <cuda_runtime.h>
#include <stdint.h>
#include <math.h>

#define BB 1024
#define SS 100
#define HH 256
#define GG 1024            // 4*H
#define BSs (BB*SS)        // 102400

// ---------------- scratch ----------------
__device__ float g_embedded[(size_t)BSs*HH];
__device__ float g_xg[(size_t)BSs*GG];         // emb@wih^T + bih
__device__ float g_enc_out[(size_t)BSs*HH];
__device__ float g_ref_g[(size_t)BSs*HH];
__device__ float g_ref_p[(size_t)BSs*HH];
__device__ float g_h[BB*HH];
__device__ float g_c[BB*HH];
__device__ float g_gates[BB*GG];
__device__ float g_q[BB*HH];
__device__ float g_qw[BB*HH];
__device__ float g_dec_in[BB*HH];
__device__ unsigned char g_mask[BSs];
__device__ uint2 g_keys[SS];

// ---------------- XLA elemental tanh, FMA-contracted Horner ----------------
__device__ __forceinline__ float tanhx(float x){
    float xc = fminf(fmaxf(x, -9.0f), 9.0f);
    float x2 = __fmul_rn(xc, xc);
    float p = -2.76076847742355e-16f;
    p = fmaf(p, x2,  2.00018790482477e-13f);
    p = fmaf(p, x2, -8.60467152213735e-11f);
    p = fmaf(p, x2,  5.12229709037114e-08f);
    p = fmaf(p, x2,  1.48572235717979e-05f);
    p = fmaf(p, x2,  6.37261928875436e-04f);
    p = fmaf(p, x2,  4.89352455891786e-03f);
    float num = __fmul_rn(xc, p);
    float q = 1.19825839466702e-06f;
    q = fmaf(q, x2, 1.18534705686654e-04f);
    q = fmaf(q, x2, 2.26843463243900e-03f);
    q = fmaf(q, x2, 4.89352518554385e-03f);
    float r = __fdiv_rn(num, q);
    return (fabsf(x) < 0.0004f) ? x : r;
}
// XLA logistic expander: fma(0.5, tanh(0.5x), 0.5)
__device__ __forceinline__ float sigx(float x){
    float t = tanhx(__fmul_rn(0.5f, x));
    return fmaf(0.5f, t, 0.5f);
}
// near-correctly-rounded f32 exp/log via double (glibc-class)
__device__ __forceinline__ float expd(float x){ return (float)exp((double)x); }
__device__ __forceinline__ float logd(float x){ return (float)log((double)x); }

// ---------------- threefry2x32 core ----------------
__device__ __forceinline__ uint32_t rotl32(uint32_t x, int d){ return (x<<d)|(x>>(32-d)); }
__device__ __forceinline__ void threefry2x32(uint32_t k0, uint32_t k1, uint32_t& x0, uint32_t& x1){
    uint32_t ks2 = k0 ^ k1 ^ 0x1BD11BDAu;
    x0 += k0; x1 += k1;
    #define TF_R4(a,b,c,d) \
        x0 += x1; x1 = rotl32(x1,a); x1 ^= x0; \
        x0 += x1; x1 = rotl32(x1,b); x1 ^= x0; \
        x0 += x1; x1 = rotl32(x1,c); x1 ^= x0; \
        x0 += x1; x1 = rotl32(x1,d); x1 ^= x0;
    TF_R4(13,15,26,6);  x0 += k1;  x1 += ks2 + 1u;
    TF_R4(17,29,16,24); x0 += ks2; x1 += k0  + 2u;
    TF_R4(13,15,26,6);  x0 += k0;  x1 += k1  + 3u;
    TF_R4(17,29,16,24); x0 += k1;  x1 += ks2 + 4u;
    TF_R4(13,15,26,6);  x0 += ks2; x1 += k0  + 5u;
    #undef TF_R4
}

// ---------------- PARTITIONABLE threefry key split (jax >= 0.4.36 default) ----------
// split(key, n): 64-bit iota j -> counts (hi=0, lo=j); keys[j] = (lane0, lane1)
__global__ void keys_kernel(){
    int t = threadIdx.x;
    if (t < SS){
        uint32_t x0 = 0u, x1 = (uint32_t)t;
        threefry2x32(0u, 42u, x0, x1);
        g_keys[t] = make_uint2(x0, x1);
    }
}

__global__ void init_kernel(const float* __restrict__ start){
    int i = blockIdx.x*blockDim.x + threadIdx.x;
    if (i < BB*HH){ g_h[i]=0.f; g_c[i]=0.f; g_dec_in[i] = start[i & (HH-1)]; }
    if (i < BSs)    g_mask[i] = 0;
}

// embedded = inputs @ emb_w^T + emb_b
__global__ void embed_kernel(const float* __restrict__ inp, const float* __restrict__ w,
                             const float* __restrict__ bias){
    size_t i = (size_t)blockIdx.x*blockDim.x + threadIdx.x;
    int h = (int)(i & (HH-1));
    size_t bs = i >> 8;
    float acc = fmaf(inp[bs*2+1], w[h*2+1], __fmul_rn(inp[bs*2], w[h*2]));
    g_embedded[i] = __fadd_rn(acc, bias[h]);
}

// ---------------- fp32 GEMM: per-output sequential-k fma chains ----------------
__global__ void __launch_bounds__(256)
gemm_kernel(const float* __restrict__ A1, const float* __restrict__ W1, int K1,
            const float* __restrict__ bias1,
            const float* __restrict__ A2, const float* __restrict__ W2, int K2,
            const float* __restrict__ bias2,
            const float* __restrict__ addend, long long addStride,
            float* __restrict__ C, int N){
    __shared__ float As[32][65];
    __shared__ float Wsm[32][65];
    int tid = threadIdx.x;
    int tx = tid & 15, ty = tid >> 4;
    int n0 = blockIdx.x * 64, m0 = blockIdx.y * 64;
    float acc1[4][4] = {};
    float acc2[4][4] = {};
    for (int kt = 0; kt < K1; kt += 32){
        #pragma unroll
        for (int e = 0; e < 8; e++){
            int idx = tid + e*256;
            int k = idx & 31, r = idx >> 5;
            As[k][r]  = A1[(size_t)(m0 + r)*K1 + kt + k];
            Wsm[k][r] = W1[(size_t)(n0 + r)*K1 + kt + k];
        }
        __syncthreads();
        #pragma unroll
        for (int kk = 0; kk < 32; kk++){
            float a[4], w[4];
            #pragma unroll
            for (int i = 0; i < 4; i++) a[i] = As[kk][ty*4+i];
            #pragma unroll
            for (int j = 0; j < 4; j++) w[j] = Wsm[kk][tx*4+j];
            #pragma unroll
            for (int i = 0; i < 4; i++)
                #pragma unroll
                for (int j = 0; j < 4; j++)
                    acc1[i][j] = fmaf(a[i], w[j], acc1[i][j]);
        }
        __syncthreads();
    }
    for (int kt = 0; kt < K2; kt += 32){
        #pragma unroll
        for (int e = 0; e < 8; e++){
            int idx = tid + e*256;
            int k = idx & 31, r = idx >> 5;
            As[k][r]  = A2[(size_t)(m0 + r)*K2 + kt + k];
            Wsm[k][r] = W2[(size_t)(n0 + r)*K2 + kt + k];
        }
        __syncthreads();
        #pragma unroll
        for (int kk = 0; kk < 32; kk++){
            float a[4], w[4];
            #pragma unroll
            for (int i = 0; i < 4; i++) a[i] = As[kk][ty*4+i];
            #pragma unroll
            for (int j = 0; j < 4; j++) w[j] = Wsm[kk][tx*4+j];
            #pragma unroll
            for (int i = 0; i < 4; i++)
                #pragma unroll
                for (int j = 0; j < 4; j++)
                    acc2[i][j] = fmaf(a[i], w[j], acc2[i][j]);
        }
        __syncthreads();
    }
    #pragma unroll
    for (int i = 0; i < 4; i++){
        int r = m0 + ty*4 + i;
        #pragma unroll
        for (int j = 0; j < 4; j++){
            int n = n0 + tx*4 + j;
            float v = acc1[i][j];
            if (bias1)  v = __fadd_rn(v, bias1[n]);
            if (addend) v = __fadd_rn(addend[(size_t)r*addStride + n], v);
            if (A2)     v = __fadd_rn(v, acc2[i][j]);
            if (bias2)  v = __fadd_rn(v, bias2[n]);
            C[(size_t)r*N + n] = v;
        }
    }
}

// ---------------- LSTM cell (torch order i,f,g,o) ----------------
__global__ void cell_kernel(const float* __restrict__ gates, float* __restrict__ h,
                            float* __restrict__ c, float* __restrict__ enc_slice){
    int i = blockIdx.x*blockDim.x + threadIdx.x;
    int b = i >> 8, hh = i & 255;
    const float* gb = gates + (size_t)b*GG;
    float si = sigx(gb[hh]);
    float sf = sigx(gb[HH+hh]);
    float tg = tanhx(gb[2*HH+hh]);
    float so = sigx(gb[3*HH+hh]);
    float cn = fmaf(sf, c[i], __fmul_rn(si, tg));
    float hn = __fmul_rn(so, tanhx(cn));
    c[i] = cn; h[i] = hn;
    if (enc_slice) enc_slice[(size_t)b*SS*HH + hh] = hn;
}

// ---------------- attention ----------------
__global__ void __launch_bounds__(256)
attn_kernel(const float* __restrict__ qw_all, const float* __restrict__ vw,
            const float* __restrict__ vb, const float* __restrict__ refp,
            int do_sample, int step, float* __restrict__ out){
    int b = blockIdx.x, t = threadIdx.x;
    __shared__ float qs[HH], vs[HH];
    __shared__ float sl[SS], sp[SS], se[SS];
    __shared__ float sstat[2];
    __shared__ int   schosen;

    qs[t] = qw_all[(size_t)b*HH + t];
    vs[t] = vw[t];
    __syncthreads();

    const float* refb = refp + (size_t)b*SS*HH;
    const unsigned char* maskb = g_mask + (size_t)b*SS;

    // logits: sequential-k fma chain over h ascending
    if (t < SS){
        const float* r = refb + (size_t)t*HH;
        float acc = 0.f;
        for (int h = 0; h < HH; h++){
            float u = tanhx(__fadd_rn(r[h], qs[h]));
            acc = fmaf(u, vs[h], acc);
        }
        float tot = __fadd_rn(acc, vb[0]);
        float lg = maskb[t] ? -100000.0f : tot;
        sl[t] = __fmul_rn(10.0f, tanhx(lg));
    }
    __syncthreads();
    if (t == 0){
        float m = sl[0];
        for (int s = 1; s < SS; s++) m = fmaxf(m, sl[s]);
        sstat[0] = m;
    }
    __syncthreads();
    float m = sstat[0];

    if (!do_sample){
        if (t < SS) se[t] = expd(__fsub_rn(sl[t], m));
        __syncthreads();
        if (t == 0){
            float ssum = 0.f;
            for (int s = 0; s < SS; s++) ssum = __fadd_rn(ssum, se[s]);
            sstat[1] = ssum;
        }
        __syncthreads();
        if (t < SS) sp[t] = __fdiv_rn(se[t], sstat[1]);
        __syncthreads();
        const float* encb = g_enc_out + (size_t)b*SS*HH;
        float acc = 0.f;
        for (int s = 0; s < SS; s++)
            acc = fmaf(sp[s], encb[(size_t)s*HH + t], acc);
        g_q[(size_t)b*HH + t] = acc;
    } else {
        if (t < SS){
            // PARTITIONABLE random_bits: count = (hi=0, lo=flat index); bits = lane0 ^ lane1
            uint2 key = g_keys[step];
            uint32_t x0 = 0u, x1 = (uint32_t)(b*SS + t);
            threefry2x32(key.x, key.y, x0, x1);
            uint32_t bits = x0 ^ x1;
            float f = __uint_as_float((bits >> 9) | 0x3f800000u) - 1.0f;
            const float tiny = 1.1754943508222875e-38f;
            float u = fmaxf(tiny, __fadd_rn(f, tiny));
            float gmb = -logd(-logd(u));
            sp[t] = __fadd_rn(sl[t], gmb);
            se[t] = expd(__fsub_rn(sl[t], m));
        }
        __syncthreads();
        if (t == 0){
            float ssum = 0.f;
            for (int s = 0; s < SS; s++) ssum = __fadd_rn(ssum, se[s]);
            float lse = logd(ssum);
            float best = sp[0]; int bi = 0;
            for (int s = 1; s < SS; s++) if (sp[s] > best){ best = sp[s]; bi = s; }
            schosen = bi;
            float lp = __fsub_rn(__fsub_rn(sl[bi], m), lse);
            out[(size_t)b*SS + step] = lp;
            out[(size_t)BSs + (size_t)b*SS + step] = (float)bi;   // chosen as FLOAT value
            g_mask[(size_t)b*SS + bi] = 1;
        }
        __syncthreads();
        int ch = schosen;
        g_dec_in[(size_t)b*HH + t] = g_embedded[((size_t)b*SS + ch)*HH + t];
    }
}

// ---------------- host ----------------
extern "C" void kernel_launch(void* const* d_in, const int* in_sizes, int n_in,
                              void* d_out, int out_size){
    (void)in_sizes; (void)n_in; (void)out_size;
    const float* inputs    = (const float*)d_in[0];
    const float* emb_w     = (const float*)d_in[1];
    const float* emb_b     = (const float*)d_in[2];
    const float* enc_wih   = (const float*)d_in[3];
    const float* enc_whh   = (const float*)d_in[4];
    const float* enc_bih   = (const float*)d_in[5];
    const float* enc_bhh   = (const float*)d_in[6];
    const float* dec_wih   = (const float*)d_in[7];
    const float* dec_whh   = (const float*)d_in[8];
    const float* dec_bih   = (const float*)d_in[9];
    const float* dec_bhh   = (const float*)d_in[10];
    const float* ptr_wq_w  = (const float*)d_in[11];
    const float* ptr_wq_b  = (const float*)d_in[12];
    const float* ptr_wref_w= (const float*)d_in[13];
    const float* ptr_wref_b= (const float*)d_in[14];
    const float* ptr_v_w   = (const float*)d_in[15];
    const float* ptr_v_b   = (const float*)d_in[16];
    const float* glm_wq_w  = (const float*)d_in[17];
    const float* glm_wq_b  = (const float*)d_in[18];
    const float* glm_wref_w= (const float*)d_in[19];
    const float* glm_wref_b= (const float*)d_in[20];
    const float* glm_v_w   = (const float*)d_in[21];
    const float* glm_v_b   = (const float*)d_in[22];
    const float* start     = (const float*)d_in[23];
    float* out = (float*)d_out;

    float *p_emb, *p_xg, *p_enc, *p_refg, *p_refp, *p_h, *p_c, *p_gates, *p_q, *p_qw, *p_din;
    cudaGetSymbolAddress((void**)&p_emb,  g_embedded);
    cudaGetSymbolAddress((void**)&p_xg,   g_xg);
    cudaGetSymbolAddress((void**)&p_enc,  g_enc_out);
    cudaGetSymbolAddress((void**)&p_refg, g_ref_g);
    cudaGetSymbolAddress((void**)&p_refp, g_ref_p);
    cudaGetSymbolAddress((void**)&p_h,    g_h);
    cudaGetSymbolAddress((void**)&p_c,    g_c);
    cudaGetSymbolAddress((void**)&p_gates,g_gates);
    cudaGetSymbolAddress((void**)&p_q,    g_q);
    cudaGetSymbolAddress((void**)&p_qw,   g_qw);
    cudaGetSymbolAddress((void**)&p_din,  g_dec_in);

    init_kernel<<<(BB*HH+255)/256, 256>>>(start);
    keys_kernel<<<1, 128>>>();
    embed_kernel<<<(unsigned)(((size_t)BSs*HH)/256), 256>>>(inputs, emb_w, emb_b);

    // xg = emb @ wih^T + bih
    gemm_kernel<<<dim3(GG/64, BSs/64), 256>>>(p_emb, enc_wih, HH, enc_bih,
                                              nullptr, nullptr, 0, nullptr,
                                              nullptr, 0, p_xg, GG);
    // encoder: gates = (xg + h@whh^T) + bhh
    for (int s = 0; s < SS; s++){
        gemm_kernel<<<dim3(GG/64, BB/64), 256>>>(p_h, enc_whh, HH, nullptr,
                                                 nullptr, nullptr, 0, enc_bhh,
                                                 p_xg + (size_t)s*GG, (long long)SS*GG,
                                                 p_gates, GG);
        cell_kernel<<<(BB*HH)/256, 256>>>(p_gates, p_h, p_c, p_enc + (size_t)s*HH);
    }
    gemm_kernel<<<dim3(HH/64, BSs/64), 256>>>(p_enc, glm_wref_w, HH, glm_wref_b,
                                              nullptr, nullptr, 0, nullptr,
                                              nullptr, 0, p_refg, HH);
    gemm_kernel<<<dim3(HH/64, BSs/64), 256>>>(p_enc, ptr_wref_w, HH, ptr_wref_b,
                                              nullptr, nullptr, 0, nullptr,
                                              nullptr, 0, p_refp, HH);
    // decoder
    for (int k = 0; k < SS; k++){
        gemm_kernel<<<dim3(GG/64, BB/64), 256>>>(p_din, dec_wih, HH, dec_bih,
                                                 p_h, dec_whh, HH, dec_bhh,
                                                 nullptr, 0, p_gates, GG);
        cell_kernel<<<(BB*HH)/256, 256>>>(p_gates, p_h, p_c, nullptr);
        gemm_kernel<<<dim3(HH/64, BB/64), 256>>>(p_h, glm_wq_w, HH, glm_wq_b,
                                                 nullptr, nullptr, 0, nullptr,
                                                 nullptr, 0, p_qw, HH);
        attn_kernel<<<BB, 256>>>(p_qw, glm_v_w, glm_v_b, p_refg, 0, k, out);
        gemm_kernel<<<dim3(HH/64, BB/64), 256>>>(p_q, ptr_wq_w, HH, ptr_wq_b,
                                                 nullptr, nullptr, 0, nullptr,
                                                 nullptr, 0, p_qw, HH);
        attn_kernel<<<BB, 256>>>(p_qw, ptr_v_w, ptr_v_b, p_refp, 1, k, out);
    }
}

// round 13
// speedup vs baseline: 1.2146x; 1.2146x over previous
#include <cuda_runtime.h>
#include <stdint.h>
#include <math.h>

#define BB 1024
#define SS 100
#define HH 256
#define GG 1024            // 4*H
#define BSs (BB*SS)        // 102400
#define REF_PAD 257        // smem row stride for ref staging (conflict-free)
#define ATTN_SMEM (SS*REF_PAD*4)

// ---------------- scratch ----------------
__device__ float g_embedded[(size_t)BSs*HH];
__device__ float g_enc_out[(size_t)BSs*HH];
__device__ float g_ref_g[(size_t)BSs*HH];
__device__ float g_ref_p[(size_t)BSs*HH];
__device__ float g_h[BB*HH];
__device__ float g_c[BB*HH];
__device__ float g_gates[BB*GG];
__device__ float g_q[BB*HH];
__device__ float g_qw[BB*HH];
__device__ float g_dec_in[BB*HH];
__device__ unsigned char g_mask[BSs];
__device__ uint2 g_keys[SS];

// ---------------- XLA elemental tanh, FMA-contracted Horner ----------------
__device__ __forceinline__ float tanhx(float x){
    float xc = fminf(fmaxf(x, -9.0f), 9.0f);
    float x2 = __fmul_rn(xc, xc);
    float p = -2.76076847742355e-16f;
    p = fmaf(p, x2,  2.00018790482477e-13f);
    p = fmaf(p, x2, -8.60467152213735e-11f);
    p = fmaf(p, x2,  5.12229709037114e-08f);
    p = fmaf(p, x2,  1.48572235717979e-05f);
    p = fmaf(p, x2,  6.37261928875436e-04f);
    p = fmaf(p, x2,  4.89352455891786e-03f);
    float num = __fmul_rn(xc, p);
    float q = 1.19825839466702e-06f;
    q = fmaf(q, x2, 1.18534705686654e-04f);
    q = fmaf(q, x2, 2.26843463243900e-03f);
    q = fmaf(q, x2, 4.89352518554385e-03f);
    float r = __fdiv_rn(num, q);
    return (fabsf(x) < 0.0004f) ? x : r;
}
__device__ __forceinline__ float sigx(float x){
    float t = tanhx(__fmul_rn(0.5f, x));
    return fmaf(0.5f, t, 0.5f);
}
__device__ __forceinline__ float expd(float x){ return (float)exp((double)x); }
__device__ __forceinline__ float logd(float x){ return (float)log((double)x); }

// ---------------- threefry2x32 core ----------------
__device__ __forceinline__ uint32_t rotl32(uint32_t x, int d){ return (x<<d)|(x>>(32-d)); }
__device__ __forceinline__ void threefry2x32(uint32_t k0, uint32_t k1, uint32_t& x0, uint32_t& x1){
    uint32_t ks2 = k0 ^ k1 ^ 0x1BD11BDAu;
    x0 += k0; x1 += k1;
    #define TF_R4(a,b,c,d) \
        x0 += x1; x1 = rotl32(x1,a); x1 ^= x0; \
        x0 += x1; x1 = rotl32(x1,b); x1 ^= x0; \
        x0 += x1; x1 = rotl32(x1,c); x1 ^= x0; \
        x0 += x1; x1 = rotl32(x1,d); x1 ^= x0;
    TF_R4(13,15,26,6);  x0 += k1;  x1 += ks2 + 1u;
    TF_R4(17,29,16,24); x0 += ks2; x1 += k0  + 2u;
    TF_R4(13,15,26,6);  x0 += k0;  x1 += k1  + 3u;
    TF_R4(17,29,16,24); x0 += k1;  x1 += ks2 + 4u;
    TF_R4(13,15,26,6);  x0 += ks2; x1 += k0  + 5u;
    #undef TF_R4
}

// PARTITIONABLE split: counts (0, j); keys[j] = (lane0, lane1)
__global__ void keys_kernel(){
    int t = threadIdx.x;
    if (t < SS){
        uint32_t x0 = 0u, x1 = (uint32_t)t;
        threefry2x32(0u, 42u, x0, x1);
        g_keys[t] = make_uint2(x0, x1);
    }
}

__global__ void init_kernel(const float* __restrict__ start){
    int i = blockIdx.x*blockDim.x + threadIdx.x;
    if (i < BB*HH){ g_h[i]=0.f; g_c[i]=0.f; g_dec_in[i] = start[i & (HH-1)]; }
    if (i < BSs)    g_mask[i] = 0;
}

// embedded = inputs @ emb_w^T + emb_b
__global__ void embed_kernel(const float* __restrict__ inp, const float* __restrict__ w,
                             const float* __restrict__ bias){
    size_t i = (size_t)blockIdx.x*blockDim.x + threadIdx.x;
    int h = (int)(i & (HH-1));
    size_t bs = i >> 8;
    float acc = fmaf(inp[bs*2+1], w[h*2+1], __fmul_rn(inp[bs*2], w[h*2]));
    g_embedded[i] = __fadd_rn(acc, bias[h]);
}

// ---------------- fp32 GEMM: per-output sequential-k fma chains ----------------
// C[r,n] = ((A1[r]:W1[n] + bias1[n]) + A2[r]:W2[n]) + bias2[n]   (each term optional)
__global__ void __launch_bounds__(256)
gemm_kernel(const float* __restrict__ A1, long long lda1,
            const float* __restrict__ W1, int K1, const float* __restrict__ bias1,
            const float* __restrict__ A2, long long lda2,
            const float* __restrict__ W2, int K2, const float* __restrict__ bias2,
            float* __restrict__ C, int N){
    __shared__ float As[32][65];
    __shared__ float Wsm[32][65];
    int tid = threadIdx.x;
    int tx = tid & 15, ty = tid >> 4;
    int n0 = blockIdx.x * 64, m0 = blockIdx.y * 64;
    float acc1[4][4] = {};
    float acc2[4][4] = {};
    for (int kt = 0; kt < K1; kt += 32){
        #pragma unroll
        for (int e = 0; e < 8; e++){
            int idx = tid + e*256;
            int k = idx & 31, r = idx >> 5;
            As[k][r]  = A1[(size_t)(m0 + r)*lda1 + kt + k];
            Wsm[k][r] = W1[(size_t)(n0 + r)*K1 + kt + k];
        }
        __syncthreads();
        #pragma unroll
        for (int kk = 0; kk < 32; kk++){
            float a[4], w[4];
            #pragma unroll
            for (int i = 0; i < 4; i++) a[i] = As[kk][ty*4+i];
            #pragma unroll
            for (int j = 0; j < 4; j++) w[j] = Wsm[kk][tx*4+j];
            #pragma unroll
            for (int i = 0; i < 4; i++)
                #pragma unroll
                for (int j = 0; j < 4; j++)
                    acc1[i][j] = fmaf(a[i], w[j], acc1[i][j]);
        }
        __syncthreads();
    }
    for (int kt = 0; kt < K2; kt += 32){
        #pragma unroll
        for (int e = 0; e < 8; e++){
            int idx = tid + e*256;
            int k = idx & 31, r = idx >> 5;
            As[k][r]  = A2[(size_t)(m0 + r)*lda2 + kt + k];
            Wsm[k][r] = W2[(size_t)(n0 + r)*K2 + kt + k];
        }
        __syncthreads();
        #pragma unroll
        for (int kk = 0; kk < 32; kk++){
            float a[4], w[4];
            #pragma unroll
            for (int i = 0; i < 4; i++) a[i] = As[kk][ty*4+i];
            #pragma unroll
            for (int j = 0; j < 4; j++) w[j] = Wsm[kk][tx*4+j];
            #pragma unroll
            for (int i = 0; i < 4; i++)
                #pragma unroll
                for (int j = 0; j < 4; j++)
                    acc2[i][j] = fmaf(a[i], w[j], acc2[i][j]);
        }
        __syncthreads();
    }
    #pragma unroll
    for (int i = 0; i < 4; i++){
        int r = m0 + ty*4 + i;
        #pragma unroll
        for (int j = 0; j < 4; j++){
            int n = n0 + tx*4 + j;
            float v = acc1[i][j];
            if (bias1)  v = __fadd_rn(v, bias1[n]);
            if (A2)     v = __fadd_rn(v, acc2[i][j]);
            if (bias2)  v = __fadd_rn(v, bias2[n]);
            C[(size_t)r*N + n] = v;
        }
    }
}

// ---------------- LSTM cell (torch order i,f,g,o) ----------------
__global__ void cell_kernel(const float* __restrict__ gates, float* __restrict__ h,
                            float* __restrict__ c, float* __restrict__ enc_slice){
    int i = blockIdx.x*blockDim.x + threadIdx.x;
    int b = i >> 8, hh = i & 255;
    const float* gb = gates + (size_t)b*GG;
    float si = sigx(gb[hh]);
    float sf = sigx(gb[HH+hh]);
    float tg = tanhx(gb[2*HH+hh]);
    float so = sigx(gb[3*HH+hh]);
    float cn = fmaf(sf, c[i], __fmul_rn(si, tg));
    float hn = __fmul_rn(so, tanhx(cn));
    c[i] = cn; h[i] = hn;
    if (enc_slice) enc_slice[(size_t)b*SS*HH + hh] = hn;
}

// ---------------- attention (smem-staged ref, coalesced) ----------------
__global__ void __launch_bounds__(256)
attn_kernel(const float* __restrict__ qw_all, const float* __restrict__ vw,
            const float* __restrict__ vb, const float* __restrict__ refp,
            int do_sample, int step, float* __restrict__ out){
    extern __shared__ float sref[];                 // [SS][REF_PAD]
    int b = blockIdx.x, t = threadIdx.x;
    __shared__ float qs[HH], vs[HH];
    __shared__ float sl[SS], sp[SS], se[SS];
    __shared__ float rv[128];
    __shared__ int   ri[128];
    __shared__ float sstat[2];
    __shared__ int   schosen;

    qs[t] = qw_all[(size_t)b*HH + t];
    vs[t] = vw[t];

    // stage ref[b] into smem: coalesced float4 global loads, padded rows
    const float* refb = refp + (size_t)b*SS*HH;
    const float4* ref4 = (const float4*)refb;
    #pragma unroll
    for (int i4 = t; i4 < SS*HH/4; i4 += 256){
        float4 v = ref4[i4];
        int flat = i4 * 4;
        int s = flat >> 8, h = flat & 255;
        float* d = sref + s*REF_PAD + h;
        d[0]=v.x; d[1]=v.y; d[2]=v.z; d[3]=v.w;
    }
    __syncthreads();

    const unsigned char* maskb = g_mask + (size_t)b*SS;

    // logits: identical sequential-k fma chain over h ascending, from smem
    if (t < SS){
        const float* r = sref + (size_t)t*REF_PAD;
        float acc = 0.f;
        for (int h = 0; h < HH; h++){
            float u = tanhx(__fadd_rn(r[h], qs[h]));
            acc = fmaf(u, vs[h], acc);
        }
        float tot = __fadd_rn(acc, vb[0]);
        float lg = maskb[t] ? -100000.0f : tot;
        sl[t] = __fmul_rn(10.0f, tanhx(lg));
    }
    __syncthreads();

    // parallel max (exact: fmaxf associative)
    if (t < 128) rv[t] = (t < SS) ? sl[t] : -3.402823466e+38f;
    __syncthreads();
    for (int st = 64; st >= 1; st >>= 1){
        if (t < st) rv[t] = fmaxf(rv[t], rv[t+st]);
        __syncthreads();
    }
    float m = rv[0];
    __syncthreads();

    if (!do_sample){
        if (t < SS) se[t] = expd(__fsub_rn(sl[t], m));
        __syncthreads();
        if (t == 0){
            float ssum = 0.f;
            for (int s = 0; s < SS; s++) ssum = __fadd_rn(ssum, se[s]);
            sstat[1] = ssum;
        }
        __syncthreads();
        if (t < SS) sp[t] = __fdiv_rn(se[t], sstat[1]);
        __syncthreads();
        const float* encb = g_enc_out + (size_t)b*SS*HH;
        float acc = 0.f;
        for (int s = 0; s < SS; s++)
            acc = fmaf(sp[s], encb[(size_t)s*HH + t], acc);
        g_q[(size_t)b*HH + t] = acc;
    } else {
        if (t < SS){
            // PARTITIONABLE random_bits: count (0, flat); bits = lane0 ^ lane1
            uint2 key = g_keys[step];
            uint32_t x0 = 0u, x1 = (uint32_t)(b*SS + t);
            threefry2x32(key.x, key.y, x0, x1);
            uint32_t bits = x0 ^ x1;
            float f = __uint_as_float((bits >> 9) | 0x3f800000u) - 1.0f;
            const float tiny = 1.1754943508222875e-38f;
            float u = fmaxf(tiny, __fadd_rn(f, tiny));
            float gmb = -logd(-logd(u));
            sp[t] = __fadd_rn(sl[t], gmb);
            se[t] = expd(__fsub_rn(sl[t], m));
        }
        __syncthreads();
        // parallel argmax, first-index tie-break (exact)
        if (t < 128){
            rv[t] = (t < SS) ? sp[t] : -3.402823466e+38f;
            ri[t] = t;
        }
        __syncthreads();
        for (int st = 64; st >= 1; st >>= 1){
            if (t < st){
                float a = rv[t], bv = rv[t+st];
                int   ib = ri[t+st];
                if (bv > a || (bv == a && ib < ri[t])){ rv[t] = bv; ri[t] = ib; }
            }
            __syncthreads();
        }
        if (t == 0){
            int bi = ri[0];
            float ssum = 0.f;
            for (int s = 0; s < SS; s++) ssum = __fadd_rn(ssum, se[s]);
            float lse = logd(ssum);
            schosen = bi;
            float lp = __fsub_rn(__fsub_rn(sl[bi], m), lse);
            out[(size_t)b*SS + step] = lp;
            out[(size_t)BSs + (size_t)b*SS + step] = (float)bi;
            g_mask[(size_t)b*SS + bi] = 1;
        }
        __syncthreads();
        int ch = schosen;
        g_dec_in[(size_t)b*HH + t] = g_embedded[((size_t)b*SS + ch)*HH + t];
    }
}

// ---------------- host ----------------
extern "C" void kernel_launch(void* const* d_in, const int* in_sizes, int n_in,
                              void* d_out, int out_size){
    (void)in_sizes; (void)n_in; (void)out_size;
    const float* inputs    = (const float*)d_in[0];
    const float* emb_w     = (const float*)d_in[1];
    const float* emb_b     = (const float*)d_in[2];
    const float* enc_wih   = (const float*)d_in[3];
    const float* enc_whh   = (const float*)d_in[4];
    const float* enc_bih   = (const float*)d_in[5];
    const float* enc_bhh   = (const float*)d_in[6];
    const float* dec_wih   = (const float*)d_in[7];
    const float* dec_whh   = (const float*)d_in[8];
    const float* dec_bih   = (const float*)d_in[9];
    const float* dec_bhh   = (const float*)d_in[10];
    const float* ptr_wq_w  = (const float*)d_in[11];
    const float* ptr_wq_b  = (const float*)d_in[12];
    const float* ptr_wref_w= (const float*)d_in[13];
    const float* ptr_wref_b= (const float*)d_in[14];
    const float* ptr_v_w   = (const float*)d_in[15];
    const float* ptr_v_b   = (const float*)d_in[16];
    const float* glm_wq_w  = (const float*)d_in[17];
    const float* glm_wq_b  = (const float*)d_in[18];
    const float* glm_wref_w= (const float*)d_in[19];
    const float* glm_wref_b= (const float*)d_in[20];
    const float* glm_v_w   = (const float*)d_in[21];
    const float* glm_v_b   = (const float*)d_in[22];
    const float* start     = (const float*)d_in[23];
    float* out = (float*)d_out;

    float *p_emb, *p_enc, *p_refg, *p_refp, *p_h, *p_c, *p_gates, *p_q, *p_qw, *p_din;
    cudaGetSymbolAddress((void**)&p_emb,  g_embedded);
    cudaGetSymbolAddress((void**)&p_enc,  g_enc_out);
    cudaGetSymbolAddress((void**)&p_refg, g_ref_g);
    cudaGetSymbolAddress((void**)&p_refp, g_ref_p);
    cudaGetSymbolAddress((void**)&p_h,    g_h);
    cudaGetSymbolAddress((void**)&p_c,    g_c);
    cudaGetSymbolAddress((void**)&p_gates,g_gates);
    cudaGetSymbolAddress((void**)&p_q,    g_q);
    cudaGetSymbolAddress((void**)&p_qw,   g_qw);
    cudaGetSymbolAddress((void**)&p_din,  g_dec_in);

    static int attr_done = 0;
    if (!attr_done){
        cudaFuncSetAttribute(attn_kernel, cudaFuncAttributeMaxDynamicSharedMemorySize,
                             ATTN_SMEM);
        attr_done = 1;
    }

    init_kernel<<<(BB*HH+255)/256, 256>>>(start);
    keys_kernel<<<1, 128>>>();
    embed_kernel<<<(unsigned)(((size_t)BSs*HH)/256), 256>>>(inputs, emb_w, emb_b);

    // encoder: gates = ((x@wih^T + bih) + h@whh^T) + bhh  (x folded in, no xg buffer)
    for (int s = 0; s < SS; s++){
        gemm_kernel<<<dim3(GG/64, BB/64), 256>>>(p_emb + (size_t)s*HH, (long long)SS*HH,
                                                 enc_wih, HH, enc_bih,
                                                 p_h, HH, enc_whh, HH, enc_bhh,
                                                 p_gates, GG);
        cell_kernel<<<(BB*HH)/256, 256>>>(p_gates, p_h, p_c, p_enc + (size_t)s*HH);
    }
    gemm_kernel<<<dim3(HH/64, BSs/64), 256>>>(p_enc, HH, glm_wref_w, HH, glm_wref_b,
                                              nullptr, 0, nullptr, 0, nullptr,
                                              p_refg, HH);
    gemm_kernel<<<dim3(HH/64, BSs/64), 256>>>(p_enc, HH, ptr_wref_w, HH, ptr_wref_b,
                                              nullptr, 0, nullptr, 0, nullptr,
                                              p_refp, HH);
    // decoder
    for (int k = 0; k < SS; k++){
        gemm_kernel<<<dim3(GG/64, BB/64), 256>>>(p_din, HH, dec_wih, HH, dec_bih,
                                                 p_h, HH, dec_whh, HH, dec_bhh,
                                                 p_gates, GG);
        cell_kernel<<<(BB*HH)/256, 256>>>(p_gates, p_h, p_c, nullptr);
        gemm_kernel<<<dim3(HH/64, BB/64), 256>>>(p_h, HH, glm_wq_w, HH, glm_wq_b,
                                                 nullptr, 0, nullptr, 0, nullptr,
                                                 p_qw, HH);
        attn_kernel<<<BB, 256, ATTN_SMEM>>>(p_qw, glm_v_w, glm_v_b, p_refg, 0, k, out);
        gemm_kernel<<<dim3(HH/64, BB/64), 256>>>(p_q, HH, ptr_wq_w, HH, ptr_wq_b,
                                                 nullptr, 0, nullptr, 0, nullptr,
                                                 p_qw, HH);
        attn_kernel<<<BB, 256, ATTN_SMEM>>>(p_qw, ptr_v_w, ptr_v_b, p_refp, 1, k, out);
    }
}

// round 14
// speedup vs baseline: 1.2974x; 1.0681x over previous
#include <cuda_runtime.h>
#include <stdint.h>
#include <math.h>

#define BB 1024
#define SS 100
#define HH 256
#define GG 1024            // 4*H
#define BSs (BB*SS)        // 102400
#define REF_PAD 257        // smem row stride for ref staging (conflict-free)
#define ATTN_SMEM (SS*REF_PAD*4)

// ---------------- scratch ----------------
__device__ float g_embedded[(size_t)BSs*HH];
__device__ float g_enc_out[(size_t)BSs*HH];
__device__ float g_ref_g[(size_t)BSs*HH];
__device__ float g_ref_p[(size_t)BSs*HH];
__device__ float g_h[BB*HH];
__device__ float g_c[BB*HH];
__device__ float g_gates[BB*GG];
__device__ float g_q[BB*HH];
__device__ float g_qw[BB*HH];
__device__ float g_dec_in[BB*HH];
__device__ unsigned char g_mask[BSs];
__device__ uint2 g_keys[SS];

// ---------------- XLA elemental tanh, FMA-contracted Horner ----------------
__device__ __forceinline__ float tanhx(float x){
    float xc = fminf(fmaxf(x, -9.0f), 9.0f);
    float x2 = __fmul_rn(xc, xc);
    float p = -2.76076847742355e-16f;
    p = fmaf(p, x2,  2.00018790482477e-13f);
    p = fmaf(p, x2, -8.60467152213735e-11f);
    p = fmaf(p, x2,  5.12229709037114e-08f);
    p = fmaf(p, x2,  1.48572235717979e-05f);
    p = fmaf(p, x2,  6.37261928875436e-04f);
    p = fmaf(p, x2,  4.89352455891786e-03f);
    float num = __fmul_rn(xc, p);
    float q = 1.19825839466702e-06f;
    q = fmaf(q, x2, 1.18534705686654e-04f);
    q = fmaf(q, x2, 2.26843463243900e-03f);
    q = fmaf(q, x2, 4.89352518554385e-03f);
    float r = __fdiv_rn(num, q);
    return (fabsf(x) < 0.0004f) ? x : r;
}
__device__ __forceinline__ float sigx(float x){
    float t = tanhx(__fmul_rn(0.5f, x));
    return fmaf(0.5f, t, 0.5f);
}
__device__ __forceinline__ float expd(float x){ return (float)exp((double)x); }
__device__ __forceinline__ float logd(float x){ return (float)log((double)x); }

// ---------------- threefry2x32 core ----------------
__device__ __forceinline__ uint32_t rotl32(uint32_t x, int d){ return (x<<d)|(x>>(32-d)); }
__device__ __forceinline__ void threefry2x32(uint32_t k0, uint32_t k1, uint32_t& x0, uint32_t& x1){
    uint32_t ks2 = k0 ^ k1 ^ 0x1BD11BDAu;
    x0 += k0; x1 += k1;
    #define TF_R4(a,b,c,d) \
        x0 += x1; x1 = rotl32(x1,a); x1 ^= x0; \
        x0 += x1; x1 = rotl32(x1,b); x1 ^= x0; \
        x0 += x1; x1 = rotl32(x1,c); x1 ^= x0; \
        x0 += x1; x1 = rotl32(x1,d); x1 ^= x0;
    TF_R4(13,15,26,6);  x0 += k1;  x1 += ks2 + 1u;
    TF_R4(17,29,16,24); x0 += ks2; x1 += k0  + 2u;
    TF_R4(13,15,26,6);  x0 += k0;  x1 += k1  + 3u;
    TF_R4(17,29,16,24); x0 += k1;  x1 += ks2 + 4u;
    TF_R4(13,15,26,6);  x0 += ks2; x1 += k0  + 5u;
    #undef TF_R4
}

// PARTITIONABLE split: counts (0, j); keys[j] = (lane0, lane1)
__global__ void keys_kernel(){
    int t = threadIdx.x;
    if (t < SS){
        uint32_t x0 = 0u, x1 = (uint32_t)t;
        threefry2x32(0u, 42u, x0, x1);
        g_keys[t] = make_uint2(x0, x1);
    }
}

__global__ void init_kernel(const float* __restrict__ start){
    int i = blockIdx.x*blockDim.x + threadIdx.x;
    if (i < BB*HH){ g_h[i]=0.f; g_c[i]=0.f; g_dec_in[i] = start[i & (HH-1)]; }
    if (i < BSs)    g_mask[i] = 0;
}

// embedded = inputs @ emb_w^T + emb_b
__global__ void embed_kernel(const float* __restrict__ inp, const float* __restrict__ w,
                             const float* __restrict__ bias){
    size_t i = (size_t)blockIdx.x*blockDim.x + threadIdx.x;
    int h = (int)(i & (HH-1));
    size_t bs = i >> 8;
    float acc = fmaf(inp[bs*2+1], w[h*2+1], __fmul_rn(inp[bs*2], w[h*2]));
    g_embedded[i] = __fadd_rn(acc, bias[h]);
}

// ---------------- templated fp32 GEMM: sequential-k fma chain per output --------------
// C[r,n] = ((A1[r]:W1[n] + bias1[n]) + A2[r]:W2[n]) + bias2[n]  (terms optional)
// k-major smem, padded +4 (aligned float4 reads; 4-way store conflicts accepted).
template<int BM, int BN, int TM, int TN, int NT>
__global__ void __launch_bounds__(NT)
gemm_t(const float* __restrict__ A1, long long lda1,
       const float* __restrict__ W1, int K1, const float* __restrict__ bias1,
       const float* __restrict__ A2, long long lda2,
       const float* __restrict__ W2, int K2, const float* __restrict__ bias2,
       float* __restrict__ C, int N){
    __shared__ float As[32][BM+4];
    __shared__ float Ws[32][BN+4];
    const int tid = threadIdx.x;
    const int txn = tid % (BN/TN);
    const int tym = tid / (BN/TN);
    const int n0 = blockIdx.x * BN, m0 = blockIdx.y * BM;

    float acc1[TM][TN];
    float acc2[TM][TN];
    #pragma unroll
    for (int i = 0; i < TM; i++)
        #pragma unroll
        for (int j = 0; j < TN; j++){ acc1[i][j] = 0.f; acc2[i][j] = 0.f; }

    for (int phase = 0; phase < 2; phase++){
        const float* A = (phase == 0) ? A1 : A2;
        const float* W = (phase == 0) ? W1 : W2;
        long long lda = (phase == 0) ? lda1 : lda2;
        int K = (phase == 0) ? K1 : K2;
        if (!A) continue;
        for (int kt = 0; kt < K; kt += 32){
            #pragma unroll
            for (int i = tid; i < BM*32; i += NT){
                int k = i & 31, r = i >> 5;
                As[k][r] = A[(size_t)(m0 + r)*lda + kt + k];
            }
            #pragma unroll
            for (int i = tid; i < BN*32; i += NT){
                int k = i & 31, r = i >> 5;
                Ws[k][r] = W[(size_t)(n0 + r)*K + kt + k];
            }
            __syncthreads();
            #pragma unroll
            for (int kk = 0; kk < 32; kk++){
                float a[TM], w[TN];
                #pragma unroll
                for (int v = 0; v < TM/4; v++)
                    *(float4*)(a + 4*v) = *(const float4*)(&As[kk][tym*TM + 4*v]);
                #pragma unroll
                for (int v = 0; v < TN/4; v++)
                    *(float4*)(w + 4*v) = *(const float4*)(&Ws[kk][txn*TN + 4*v]);
                if (phase == 0){
                    #pragma unroll
                    for (int i = 0; i < TM; i++)
                        #pragma unroll
                        for (int j = 0; j < TN; j++)
                            acc1[i][j] = fmaf(a[i], w[j], acc1[i][j]);
                } else {
                    #pragma unroll
                    for (int i = 0; i < TM; i++)
                        #pragma unroll
                        for (int j = 0; j < TN; j++)
                            acc2[i][j] = fmaf(a[i], w[j], acc2[i][j]);
                }
            }
            __syncthreads();
        }
    }

    #pragma unroll
    for (int i = 0; i < TM; i++){
        int r = m0 + tym*TM + i;
        #pragma unroll
        for (int jv = 0; jv < TN/4; jv++){
            float4 o;
            float* op = (float*)&o;
            #pragma unroll
            for (int u = 0; u < 4; u++){
                int j = jv*4 + u;
                int n = n0 + txn*TN + j;
                float v = acc1[i][j];
                if (bias1)  v = __fadd_rn(v, bias1[n]);
                if (A2)     v = __fadd_rn(v, acc2[i][j]);
                if (bias2)  v = __fadd_rn(v, bias2[n]);
                op[u] = v;
            }
            *(float4*)(&C[(size_t)r*N + n0 + txn*TN + jv*4]) = o;
        }
    }
}

// ---------------- LSTM cell (torch order i,f,g,o) ----------------
__global__ void cell_kernel(const float* __restrict__ gates, float* __restrict__ h,
                            float* __restrict__ c, float* __restrict__ enc_slice){
    int i = blockIdx.x*blockDim.x + threadIdx.x;
    int b = i >> 8, hh = i & 255;
    const float* gb = gates + (size_t)b*GG;
    float si = sigx(gb[hh]);
    float sf = sigx(gb[HH+hh]);
    float tg = tanhx(gb[2*HH+hh]);
    float so = sigx(gb[3*HH+hh]);
    float cn = fmaf(sf, c[i], __fmul_rn(si, tg));
    float hn = __fmul_rn(so, tanhx(cn));
    c[i] = cn; h[i] = hn;
    if (enc_slice) enc_slice[(size_t)b*SS*HH + hh] = hn;
}

// ---------------- attention (smem-staged ref, coalesced) ----------------
__global__ void __launch_bounds__(256)
attn_kernel(const float* __restrict__ qw_all, const float* __restrict__ vw,
            const float* __restrict__ vb, const float* __restrict__ refp,
            int do_sample, int step, float* __restrict__ out){
    extern __shared__ float sref[];                 // [SS][REF_PAD]
    int b = blockIdx.x, t = threadIdx.x;
    __shared__ float qs[HH], vs[HH];
    __shared__ float sl[SS], sp[SS], se[SS];
    __shared__ float rv[128];
    __shared__ int   ri[128];
    __shared__ float sstat[2];
    __shared__ int   schosen;

    qs[t] = qw_all[(size_t)b*HH + t];
    vs[t] = vw[t];

    const float* refb = refp + (size_t)b*SS*HH;
    const float4* ref4 = (const float4*)refb;
    #pragma unroll
    for (int i4 = t; i4 < SS*HH/4; i4 += 256){
        float4 v = ref4[i4];
        int flat = i4 * 4;
        int s = flat >> 8, h = flat & 255;
        float* d = sref + s*REF_PAD + h;
        d[0]=v.x; d[1]=v.y; d[2]=v.z; d[3]=v.w;
    }
    __syncthreads();

    const unsigned char* maskb = g_mask + (size_t)b*SS;

    if (t < SS){
        const float* r = sref + (size_t)t*REF_PAD;
        float acc = 0.f;
        for (int h = 0; h < HH; h++){
            float u = tanhx(__fadd_rn(r[h], qs[h]));
            acc = fmaf(u, vs[h], acc);
        }
        float tot = __fadd_rn(acc, vb[0]);
        float lg = maskb[t] ? -100000.0f : tot;
        sl[t] = __fmul_rn(10.0f, tanhx(lg));
    }
    __syncthreads();

    if (t < 128) rv[t] = (t < SS) ? sl[t] : -3.402823466e+38f;
    __syncthreads();
    for (int st = 64; st >= 1; st >>= 1){
        if (t < st) rv[t] = fmaxf(rv[t], rv[t+st]);
        __syncthreads();
    }
    float m = rv[0];
    __syncthreads();

    if (!do_sample){
        if (t < SS) se[t] = expd(__fsub_rn(sl[t], m));
        __syncthreads();
        if (t == 0){
            float ssum = 0.f;
            for (int s = 0; s < SS; s++) ssum = __fadd_rn(ssum, se[s]);
            sstat[1] = ssum;
        }
        __syncthreads();
        if (t < SS) sp[t] = __fdiv_rn(se[t], sstat[1]);
        __syncthreads();
        const float* encb = g_enc_out + (size_t)b*SS*HH;
        float acc = 0.f;
        for (int s = 0; s < SS; s++)
            acc = fmaf(sp[s], encb[(size_t)s*HH + t], acc);
        g_q[(size_t)b*HH + t] = acc;
    } else {
        if (t < SS){
            uint2 key = g_keys[step];
            uint32_t x0 = 0u, x1 = (uint32_t)(b*SS + t);
            threefry2x32(key.x, key.y, x0, x1);
            uint32_t bits = x0 ^ x1;
            float f = __uint_as_float((bits >> 9) | 0x3f800000u) - 1.0f;
            const float tiny = 1.1754943508222875e-38f;
            float u = fmaxf(tiny, __fadd_rn(f, tiny));
            float gmb = -logd(-logd(u));
            sp[t] = __fadd_rn(sl[t], gmb);
            se[t] = expd(__fsub_rn(sl[t], m));
        }
        __syncthreads();
        if (t < 128){
            rv[t] = (t < SS) ? sp[t] : -3.402823466e+38f;
            ri[t] = t;
        }
        __syncthreads();
        for (int st = 64; st >= 1; st >>= 1){
            if (t < st){
                float a = rv[t], bv = rv[t+st];
                int   ib = ri[t+st];
                if (bv > a || (bv == a && ib < ri[t])){ rv[t] = bv; ri[t] = ib; }
            }
            __syncthreads();
        }
        if (t == 0){
            int bi = ri[0];
            float ssum = 0.f;
            for (int s = 0; s < SS; s++) ssum = __fadd_rn(ssum, se[s]);
            float lse = logd(ssum);
            schosen = bi;
            float lp = __fsub_rn(__fsub_rn(sl[bi], m), lse);
            out[(size_t)b*SS + step] = lp;
            out[(size_t)BSs + (size_t)b*SS + step] = (float)bi;
            g_mask[(size_t)b*SS + bi] = 1;
        }
        __syncthreads();
        int ch = schosen;
        g_dec_in[(size_t)b*HH + t] = g_embedded[((size_t)b*SS + ch)*HH + t];
    }
}

// ---------------- host ----------------
extern "C" void kernel_launch(void* const* d_in, const int* in_sizes, int n_in,
                              void* d_out, int out_size){
    (void)in_sizes; (void)n_in; (void)out_size;
    const float* inputs    = (const float*)d_in[0];
    const float* emb_w     = (const float*)d_in[1];
    const float* emb_b     = (const float*)d_in[2];
    const float* enc_wih   = (const float*)d_in[3];
    const float* enc_whh   = (const float*)d_in[4];
    const float* enc_bih   = (const float*)d_in[5];
    const float* enc_bhh   = (const float*)d_in[6];
    const float* dec_wih   = (const float*)d_in[7];
    const float* dec_whh   = (const float*)d_in[8];
    const float* dec_bih   = (const float*)d_in[9];
    const float* dec_bhh   = (const float*)d_in[10];
    const float* ptr_wq_w  = (const float*)d_in[11];
    const float* ptr_wq_b  = (const float*)d_in[12];
    const float* ptr_wref_w= (const float*)d_in[13];
    const float* ptr_wref_b= (const float*)d_in[14];
    const float* ptr_v_w   = (const float*)d_in[15];
    const float* ptr_v_b   = (const float*)d_in[16];
    const float* glm_wq_w  = (const float*)d_in[17];
    const float* glm_wq_b  = (const float*)d_in[18];
    const float* glm_wref_w= (const float*)d_in[19];
    const float* glm_wref_b= (const float*)d_in[20];
    const float* glm_v_w   = (const float*)d_in[21];
    const float* glm_v_b   = (const float*)d_in[22];
    const float* start     = (const float*)d_in[23];
    float* out = (float*)d_out;

    float *p_emb, *p_enc, *p_refg, *p_refp, *p_h, *p_c, *p_gates, *p_q, *p_qw, *p_din;
    cudaGetSymbolAddress((void**)&p_emb,  g_embedded);
    cudaGetSymbolAddress((void**)&p_enc,  g_enc_out);
    cudaGetSymbolAddress((void**)&p_refg, g_ref_g);
    cudaGetSymbolAddress((void**)&p_refp, g_ref_p);
    cudaGetSymbolAddress((void**)&p_h,    g_h);
    cudaGetSymbolAddress((void**)&p_c,    g_c);
    cudaGetSymbolAddress((void**)&p_gates,g_gates);
    cudaGetSymbolAddress((void**)&p_q,    g_q);
    cudaGetSymbolAddress((void**)&p_qw,   g_qw);
    cudaGetSymbolAddress((void**)&p_din,  g_dec_in);

    static int attr_done = 0;
    if (!attr_done){
        cudaFuncSetAttribute(attn_kernel, cudaFuncAttributeMaxDynamicSharedMemorySize,
                             ATTN_SMEM);
        attr_done = 1;
    }

    init_kernel<<<(BB*HH+255)/256, 256>>>(start);
    keys_kernel<<<1, 128>>>();
    embed_kernel<<<(unsigned)(((size_t)BSs*HH)/256), 256>>>(inputs, emb_w, emb_b);

    // encoder: gates = ((x@wih^T + bih) + h@whh^T) + bhh
    for (int s = 0; s < SS; s++){
        gemm_t<128,64,8,4,256><<<dim3(GG/64, BB/128), 256>>>(
            p_emb + (size_t)s*HH, (long long)SS*HH, enc_wih, HH, enc_bih,
            p_h, HH, enc_whh, HH, enc_bhh, p_gates, GG);
        cell_kernel<<<(BB*HH)/256, 256>>>(p_gates, p_h, p_c, p_enc + (size_t)s*HH);
    }
    gemm_t<128,64,8,4,256><<<dim3(HH/64, BSs/128), 256>>>(
        p_enc, HH, glm_wref_w, HH, glm_wref_b,
        nullptr, 0, nullptr, 0, nullptr, p_refg, HH);
    gemm_t<128,64,8,4,256><<<dim3(HH/64, BSs/128), 256>>>(
        p_enc, HH, ptr_wref_w, HH, ptr_wref_b,
        nullptr, 0, nullptr, 0, nullptr, p_refp, HH);
    // decoder
    for (int k = 0; k < SS; k++){
        gemm_t<128,64,8,4,256><<<dim3(GG/64, BB/128), 256>>>(
            p_din, HH, dec_wih, HH, dec_bih,
            p_h, HH, dec_whh, HH, dec_bhh, p_gates, GG);
        cell_kernel<<<(BB*HH)/256, 256>>>(p_gates, p_h, p_c, nullptr);
        gemm_t<32,64,4,4,128><<<dim3(HH/64, BB/32), 128>>>(
            p_h, HH, glm_wq_w, HH, glm_wq_b,
            nullptr, 0, nullptr, 0, nullptr, p_qw, HH);
        attn_kernel<<<BB, 256, ATTN_SMEM>>>(p_qw, glm_v_w, glm_v_b, p_refg, 0, k, out);
        gemm_t<32,64,4,4,128><<<dim3(HH/64, BB/32), 128>>>(
            p_q, HH, ptr_wq_w, HH, ptr_wq_b,
            nullptr, 0, nullptr, 0, nullptr, p_qw, HH);
        attn_kernel<<<BB, 256, ATTN_SMEM>>>(p_qw, ptr_v_w, ptr_v_b, p_refp, 1, k, out);
    }
}

// round 15
// speedup vs baseline: 1.3017x; 1.0033x over previous
#include <cuda_runtime.h>
#include <stdint.h>
#include <math.h>

#define BB 1024
#define SS 100
#define HH 256
#define GG 1024            // 4*H
#define BSs (BB*SS)        // 102400
#define REF_PAD 257
#define ATTN_SMEM (SS*REF_PAD*4)

// ---------------- scratch ----------------
__device__ float g_embedded[(size_t)BSs*HH];
__device__ float g_enc_out[(size_t)BSs*HH];
__device__ float g_ref_g[(size_t)BSs*HH];
__device__ float g_ref_p[(size_t)BSs*HH];
__device__ float g_hA[BB*HH];
__device__ float g_hB[BB*HH];
__device__ float g_c[BB*HH];
__device__ float g_q[BB*HH];
__device__ float g_qw[BB*HH];
__device__ float g_dec_in[BB*HH];
__device__ unsigned char g_mask[BSs];
__device__ uint2 g_keys[SS];
// gate-interleaved weights/biases: row 4h+g <- row g*HH+h
__device__ float g_wih_e[GG*HH];
__device__ float g_whh_e[GG*HH];
__device__ float g_wih_d[GG*HH];
__device__ float g_whh_d[GG*HH];
__device__ float g_b1_e[GG];
__device__ float g_b2_e[GG];
__device__ float g_b1_d[GG];
__device__ float g_b2_d[GG];

// ---------------- XLA elemental tanh, FMA-contracted Horner ----------------
__device__ __forceinline__ float tanhx(float x){
    float xc = fminf(fmaxf(x, -9.0f), 9.0f);
    float x2 = __fmul_rn(xc, xc);
    float p = -2.76076847742355e-16f;
    p = fmaf(p, x2,  2.00018790482477e-13f);
    p = fmaf(p, x2, -8.60467152213735e-11f);
    p = fmaf(p, x2,  5.12229709037114e-08f);
    p = fmaf(p, x2,  1.48572235717979e-05f);
    p = fmaf(p, x2,  6.37261928875436e-04f);
    p = fmaf(p, x2,  4.89352455891786e-03f);
    float num = __fmul_rn(xc, p);
    float q = 1.19825839466702e-06f;
    q = fmaf(q, x2, 1.18534705686654e-04f);
    q = fmaf(q, x2, 2.26843463243900e-03f);
    q = fmaf(q, x2, 4.89352518554385e-03f);
    float r = __fdiv_rn(num, q);
    return (fabsf(x) < 0.0004f) ? x : r;
}
__device__ __forceinline__ float sigx(float x){
    float t = tanhx(__fmul_rn(0.5f, x));
    return fmaf(0.5f, t, 0.5f);
}
__device__ __forceinline__ float expd(float x){ return (float)exp((double)x); }
__device__ __forceinline__ float logd(float x){ return (float)log((double)x); }

// ---------------- threefry2x32 ----------------
__device__ __forceinline__ uint32_t rotl32(uint32_t x, int d){ return (x<<d)|(x>>(32-d)); }
__device__ __forceinline__ void threefry2x32(uint32_t k0, uint32_t k1, uint32_t& x0, uint32_t& x1){
    uint32_t ks2 = k0 ^ k1 ^ 0x1BD11BDAu;
    x0 += k0; x1 += k1;
    #define TF_R4(a,b,c,d) \
        x0 += x1; x1 = rotl32(x1,a); x1 ^= x0; \
        x0 += x1; x1 = rotl32(x1,b); x1 ^= x0; \
        x0 += x1; x1 = rotl32(x1,c); x1 ^= x0; \
        x0 += x1; x1 = rotl32(x1,d); x1 ^= x0;
    TF_R4(13,15,26,6);  x0 += k1;  x1 += ks2 + 1u;
    TF_R4(17,29,16,24); x0 += ks2; x1 += k0  + 2u;
    TF_R4(13,15,26,6);  x0 += k0;  x1 += k1  + 3u;
    TF_R4(17,29,16,24); x0 += k1;  x1 += ks2 + 4u;
    TF_R4(13,15,26,6);  x0 += ks2; x1 += k0  + 5u;
    #undef TF_R4
}

__global__ void keys_kernel(){
    int t = threadIdx.x;
    if (t < SS){
        uint32_t x0 = 0u, x1 = (uint32_t)t;
        threefry2x32(0u, 42u, x0, x1);
        g_keys[t] = make_uint2(x0, x1);
    }
}

__global__ void init_kernel(const float* __restrict__ start){
    int i = blockIdx.x*blockDim.x + threadIdx.x;
    if (i < BB*HH){ g_hA[i]=0.f; g_c[i]=0.f; g_dec_in[i] = start[i & (HH-1)]; }
    if (i < BSs)    g_mask[i] = 0;
}

// permute gate weights/biases to interleaved layout: dst row 4h+g = src row g*HH+h
__global__ void prep_kernel(const float* __restrict__ ewih, const float* __restrict__ ewhh,
                            const float* __restrict__ ebi,  const float* __restrict__ ebh,
                            const float* __restrict__ dwih, const float* __restrict__ dwhh,
                            const float* __restrict__ dbi,  const float* __restrict__ dbh){
    int i = blockIdx.x*blockDim.x + threadIdx.x;      // over GG*HH
    int np = i >> 8;          // dst row
    int k  = i & 255;
    int h  = np >> 2, g = np & 3;
    int src = ((g<<8) + h)*HH + k;
    g_wih_e[i] = ewih[src];
    g_whh_e[i] = ewhh[src];
    g_wih_d[i] = dwih[src];
    g_whh_d[i] = dwhh[src];
    if (i < GG){
        int nh = i >> 2, ng = i & 3;
        g_b1_e[i] = ebi[(ng<<8)+nh];  g_b2_e[i] = ebh[(ng<<8)+nh];
        g_b1_d[i] = dbi[(ng<<8)+nh];  g_b2_d[i] = dbh[(ng<<8)+nh];
    }
}

// embedded = inputs @ emb_w^T + emb_b
__global__ void embed_kernel(const float* __restrict__ inp, const float* __restrict__ w,
                             const float* __restrict__ bias){
    size_t i = (size_t)blockIdx.x*blockDim.x + threadIdx.x;
    int h = (int)(i & (HH-1));
    size_t bs = i >> 8;
    float acc = fmaf(inp[bs*2+1], w[h*2+1], __fmul_rn(inp[bs*2], w[h*2]));
    g_embedded[i] = __fadd_rn(acc, bias[h]);
}

// ---------------- generic GEMM (ref projections / qw) ----------------
template<int BM, int BN, int TM, int TN, int NT>
__global__ void __launch_bounds__(NT)
gemm_t(const float* __restrict__ A1, long long lda1,
       const float* __restrict__ W1, int K1, const float* __restrict__ bias1,
       float* __restrict__ C, int N){
    __shared__ float As[32][BM+4];
    __shared__ float Ws[32][BN+4];
    const int tid = threadIdx.x;
    const int txn = tid % (BN/TN);
    const int tym = tid / (BN/TN);
    const int n0 = blockIdx.x * BN, m0 = blockIdx.y * BM;
    float acc1[TM][TN];
    #pragma unroll
    for (int i = 0; i < TM; i++)
        #pragma unroll
        for (int j = 0; j < TN; j++) acc1[i][j] = 0.f;

    for (int kt = 0; kt < K1; kt += 32){
        #pragma unroll
        for (int i = tid; i < BM*32; i += NT){
            int k = i & 31, r = i >> 5;
            As[k][r] = A1[(size_t)(m0 + r)*lda1 + kt + k];
        }
        #pragma unroll
        for (int i = tid; i < BN*32; i += NT){
            int k = i & 31, r = i >> 5;
            Ws[k][r] = W1[(size_t)(n0 + r)*K1 + kt + k];
        }
        __syncthreads();
        #pragma unroll
        for (int kk = 0; kk < 32; kk++){
            float a[TM], w[TN];
            #pragma unroll
            for (int v = 0; v < TM/4; v++)
                *(float4*)(a + 4*v) = *(const float4*)(&As[kk][tym*TM + 4*v]);
            #pragma unroll
            for (int v = 0; v < TN/4; v++)
                *(float4*)(w + 4*v) = *(const float4*)(&Ws[kk][txn*TN + 4*v]);
            #pragma unroll
            for (int i = 0; i < TM; i++)
                #pragma unroll
                for (int j = 0; j < TN; j++)
                    acc1[i][j] = fmaf(a[i], w[j], acc1[i][j]);
        }
        __syncthreads();
    }
    #pragma unroll
    for (int i = 0; i < TM; i++){
        int r = m0 + tym*TM + i;
        #pragma unroll
        for (int jv = 0; jv < TN/4; jv++){
            float4 o; float* op = (float*)&o;
            #pragma unroll
            for (int u = 0; u < 4; u++){
                int n = n0 + txn*TN + jv*4 + u;
                op[u] = __fadd_rn(acc1[i][jv*4+u], bias1[n]);
            }
            *(float4*)(&C[(size_t)r*N + n0 + txn*TN + jv*4]) = o;
        }
    }
}

// ---------------- fused LSTM step: dual GEMM + cell epilogue ----------------
// Interleaved weights: column 4h+g holds gate g of hidden h.
// gates[r][n] = ((x:W1[n] + b1[n]) + hprev:W2[n]) + b2[n]; then cell per (r,h).
// BN=64, TN=4: each thread owns TM rows x 1 gate-quadruple.
template<int BM, int BN, int TM, int NT>
__global__ void __launch_bounds__(NT)
lstm_step(const float* __restrict__ A1, long long lda1,
          const float* __restrict__ W1, const float* __restrict__ b1,
          const float* __restrict__ hprev, const float* __restrict__ W2,
          const float* __restrict__ b2,
          float* __restrict__ hnext, float* __restrict__ c,
          float* __restrict__ enc_slice){
    __shared__ float As[32][BM+4];
    __shared__ float Ws[32][BN+4];
    const int tid = threadIdx.x;
    const int txn = tid % (BN/4);
    const int tym = tid / (BN/4);
    const int n0 = blockIdx.x * BN, m0 = blockIdx.y * BM;
    float acc1[TM][4];
    float acc2[TM][4];
    #pragma unroll
    for (int i = 0; i < TM; i++)
        #pragma unroll
        for (int j = 0; j < 4; j++){ acc1[i][j] = 0.f; acc2[i][j] = 0.f; }

    for (int phase = 0; phase < 2; phase++){
        const float* A = (phase == 0) ? A1 : hprev;
        const float* W = (phase == 0) ? W1 : W2;
        long long lda = (phase == 0) ? lda1 : (long long)HH;
        for (int kt = 0; kt < HH; kt += 32){
            #pragma unroll
            for (int i = tid; i < BM*32; i += NT){
                int k = i & 31, r = i >> 5;
                As[k][r] = A[(size_t)(m0 + r)*lda + kt + k];
            }
            #pragma unroll
            for (int i = tid; i < BN*32; i += NT){
                int k = i & 31, r = i >> 5;
                Ws[k][r] = W[(size_t)(n0 + r)*HH + kt + k];
            }
            __syncthreads();
            #pragma unroll
            for (int kk = 0; kk < 32; kk++){
                float a[TM], w[4];
                #pragma unroll
                for (int v = 0; v < TM/4; v++)
                    *(float4*)(a + 4*v) = *(const float4*)(&As[kk][tym*TM + 4*v]);
                *(float4*)w = *(const float4*)(&Ws[kk][txn*4]);
                if (phase == 0){
                    #pragma unroll
                    for (int i = 0; i < TM; i++)
                        #pragma unroll
                        for (int j = 0; j < 4; j++)
                            acc1[i][j] = fmaf(a[i], w[j], acc1[i][j]);
                } else {
                    #pragma unroll
                    for (int i = 0; i < TM; i++)
                        #pragma unroll
                        for (int j = 0; j < 4; j++)
                            acc2[i][j] = fmaf(a[i], w[j], acc2[i][j]);
                }
            }
            __syncthreads();
        }
    }

    int n = n0 + txn*4;
    int hidx = n >> 2;
    float b1v[4] = { b1[n], b1[n+1], b1[n+2], b1[n+3] };
    float b2v[4] = { b2[n], b2[n+1], b2[n+2], b2[n+3] };
    #pragma unroll
    for (int i = 0; i < TM; i++){
        int r = m0 + tym*TM + i;
        float v[4];
        #pragma unroll
        for (int u = 0; u < 4; u++){
            float t = acc1[i][u];
            t = __fadd_rn(t, b1v[u]);
            t = __fadd_rn(t, acc2[i][u]);
            t = __fadd_rn(t, b2v[u]);
            v[u] = t;
        }
        float si = sigx(v[0]);
        float sf = sigx(v[1]);
        float tg = tanhx(v[2]);
        float so = sigx(v[3]);
        float cold = c[(size_t)r*HH + hidx];
        float cn = fmaf(sf, cold, __fmul_rn(si, tg));
        float hn = __fmul_rn(so, tanhx(cn));
        c[(size_t)r*HH + hidx] = cn;
        hnext[(size_t)r*HH + hidx] = hn;
        if (enc_slice) enc_slice[(size_t)r*SS*HH + hidx] = hn;
    }
}

// ---------------- attention (smem-staged ref, coalesced) ----------------
__global__ void __launch_bounds__(256)
attn_kernel(const float* __restrict__ qw_all, const float* __restrict__ vw,
            const float* __restrict__ vb, const float* __restrict__ refp,
            int do_sample, int step, float* __restrict__ out){
    extern __shared__ float sref[];                 // [SS][REF_PAD]
    int b = blockIdx.x, t = threadIdx.x;
    __shared__ float qs[HH], vs[HH];
    __shared__ float sl[SS], sp[SS], se[SS];
    __shared__ float rv[128];
    __shared__ int   ri[128];
    __shared__ float sstat[2];
    __shared__ int   schosen;

    qs[t] = qw_all[(size_t)b*HH + t];
    vs[t] = vw[t];

    const float* refb = refp + (size_t)b*SS*HH;
    const float4* ref4 = (const float4*)refb;
    #pragma unroll
    for (int i4 = t; i4 < SS*HH/4; i4 += 256){
        float4 v = ref4[i4];
        int flat = i4 * 4;
        int s = flat >> 8, h = flat & 255;
        float* d = sref + s*REF_PAD + h;
        d[0]=v.x; d[1]=v.y; d[2]=v.z; d[3]=v.w;
    }
    __syncthreads();

    const unsigned char* maskb = g_mask + (size_t)b*SS;

    if (t < SS){
        const float* r = sref + (size_t)t*REF_PAD;
        float acc = 0.f;
        for (int h = 0; h < HH; h++){
            float u = tanhx(__fadd_rn(r[h], qs[h]));
            acc = fmaf(u, vs[h], acc);
        }
        float tot = __fadd_rn(acc, vb[0]);
        float lg = maskb[t] ? -100000.0f : tot;
        sl[t] = __fmul_rn(10.0f, tanhx(lg));
    }
    __syncthreads();

    if (t < 128) rv[t] = (t < SS) ? sl[t] : -3.402823466e+38f;
    __syncthreads();
    for (int st = 64; st >= 1; st >>= 1){
        if (t < st) rv[t] = fmaxf(rv[t], rv[t+st]);
        __syncthreads();
    }
    float m = rv[0];
    __syncthreads();

    if (!do_sample){
        if (t < SS) se[t] = expd(__fsub_rn(sl[t], m));
        __syncthreads();
        if (t == 0){
            float ssum = 0.f;
            for (int s = 0; s < SS; s++) ssum = __fadd_rn(ssum, se[s]);
            sstat[1] = ssum;
        }
        __syncthreads();
        if (t < SS) sp[t] = __fdiv_rn(se[t], sstat[1]);
        __syncthreads();
        const float* encb = g_enc_out + (size_t)b*SS*HH;
        float acc = 0.f;
        for (int s = 0; s < SS; s++)
            acc = fmaf(sp[s], encb[(size_t)s*HH + t], acc);
        g_q[(size_t)b*HH + t] = acc;
    } else {
        if (t < SS){
            uint2 key = g_keys[step];
            uint32_t x0 = 0u, x1 = (uint32_t)(b*SS + t);
            threefry2x32(key.x, key.y, x0, x1);
            uint32_t bits = x0 ^ x1;
            float f = __uint_as_float((bits >> 9) | 0x3f800000u) - 1.0f;
            const float tiny = 1.1754943508222875e-38f;
            float u = fmaxf(tiny, __fadd_rn(f, tiny));
            float gmb = -logd(-logd(u));
            sp[t] = __fadd_rn(sl[t], gmb);
            se[t] = expd(__fsub_rn(sl[t], m));
        }
        __syncthreads();
        if (t < 128){
            rv[t] = (t < SS) ? sp[t] : -3.402823466e+38f;
            ri[t] = t;
        }
        __syncthreads();
        for (int st = 64; st >= 1; st >>= 1){
            if (t < st){
                float a = rv[t], bv = rv[t+st];
                int   ib = ri[t+st];
                if (bv > a || (bv == a && ib < ri[t])){ rv[t] = bv; ri[t] = ib; }
            }
            __syncthreads();
        }
        if (t == 0){
            int bi = ri[0];
            float ssum = 0.f;
            for (int s = 0; s < SS; s++) ssum = __fadd_rn(ssum, se[s]);
            float lse = logd(ssum);
            schosen = bi;
            float lp = __fsub_rn(__fsub_rn(sl[bi], m), lse);
            out[(size_t)b*SS + step] = lp;
            out[(size_t)BSs + (size_t)b*SS + step] = (float)bi;
            g_mask[(size_t)b*SS + bi] = 1;
        }
        __syncthreads();
        int ch = schosen;
        g_dec_in[(size_t)b*HH + t] = g_embedded[((size_t)b*SS + ch)*HH + t];
    }
}

// ---------------- host ----------------
extern "C" void kernel_launch(void* const* d_in, const int* in_sizes, int n_in,
                              void* d_out, int out_size){
    (void)in_sizes; (void)n_in; (void)out_size;
    const float* inputs    = (const float*)d_in[0];
    const float* emb_w     = (const float*)d_in[1];
    const float* emb_b     = (const float*)d_in[2];
    const float* enc_wih   = (const float*)d_in[3];
    const float* enc_whh   = (const float*)d_in[4];
    const float* enc_bih   = (const float*)d_in[5];
    const float* enc_bhh   = (const float*)d_in[6];
    const float* dec_wih   = (const float*)d_in[7];
    const float* dec_whh   = (const float*)d_in[8];
    const float* dec_bih   = (const float*)d_in[9];
    const float* dec_bhh   = (const float*)d_in[10];
    const float* ptr_wq_w  = (const float*)d_in[11];
    const float* ptr_wq_b  = (const float*)d_in[12];
    const float* ptr_wref_w= (const float*)d_in[13];
    const float* ptr_wref_b= (const float*)d_in[14];
    const float* ptr_v_w   = (const float*)d_in[15];
    const float* ptr_v_b   = (const float*)d_in[16];
    const float* glm_wq_w  = (const float*)d_in[17];
    const float* glm_wq_b  = (const float*)d_in[18];
    const float* glm_wref_w= (const float*)d_in[19];
    const float* glm_wref_b= (const float*)d_in[20];
    const float* glm_v_w   = (const float*)d_in[21];
    const float* glm_v_b   = (const float*)d_in[22];
    const float* start     = (const float*)d_in[23];
    float* out = (float*)d_out;

    float *p_emb, *p_enc, *p_refg, *p_refp, *p_hA, *p_hB, *p_c, *p_q, *p_qw, *p_din;
    float *p_wih_e, *p_whh_e, *p_wih_d, *p_whh_d, *p_b1e, *p_b2e, *p_b1d, *p_b2d;
    cudaGetSymbolAddress((void**)&p_emb,  g_embedded);
    cudaGetSymbolAddress((void**)&p_enc,  g_enc_out);
    cudaGetSymbolAddress((void**)&p_refg, g_ref_g);
    cudaGetSymbolAddress((void**)&p_refp, g_ref_p);
    cudaGetSymbolAddress((void**)&p_hA,   g_hA);
    cudaGetSymbolAddress((void**)&p_hB,   g_hB);
    cudaGetSymbolAddress((void**)&p_c,    g_c);
    cudaGetSymbolAddress((void**)&p_q,    g_q);
    cudaGetSymbolAddress((void**)&p_qw,   g_qw);
    cudaGetSymbolAddress((void**)&p_din,  g_dec_in);
    cudaGetSymbolAddress((void**)&p_wih_e, g_wih_e);
    cudaGetSymbolAddress((void**)&p_whh_e, g_whh_e);
    cudaGetSymbolAddress((void**)&p_wih_d, g_wih_d);
    cudaGetSymbolAddress((void**)&p_whh_d, g_whh_d);
    cudaGetSymbolAddress((void**)&p_b1e, g_b1_e);
    cudaGetSymbolAddress((void**)&p_b2e, g_b2_e);
    cudaGetSymbolAddress((void**)&p_b1d, g_b1_d);
    cudaGetSymbolAddress((void**)&p_b2d, g_b2_d);

    static int attr_done = 0;
    if (!attr_done){
        cudaFuncSetAttribute(attn_kernel, cudaFuncAttributeMaxDynamicSharedMemorySize,
                             ATTN_SMEM);
        attr_done = 1;
    }

    init_kernel<<<(BB*HH+255)/256, 256>>>(start);
    keys_kernel<<<1, 128>>>();
    prep_kernel<<<(GG*HH)/256, 256>>>(enc_wih, enc_whh, enc_bih, enc_bhh,
                                      dec_wih, dec_whh, dec_bih, dec_bhh);
    embed_kernel<<<(unsigned)(((size_t)BSs*HH)/256), 256>>>(inputs, emb_w, emb_b);

    float* h_cur = p_hA;
    float* h_nxt = p_hB;
    // encoder: fused gates+cell, h double-buffered
    for (int s = 0; s < SS; s++){
        lstm_step<64,64,4,256><<<dim3(GG/64, BB/64), 256>>>(
            p_emb + (size_t)s*HH, (long long)SS*HH, p_wih_e, p_b1e,
            h_cur, p_whh_e, p_b2e,
            h_nxt, p_c, p_enc + (size_t)s*HH);
        float* tmp = h_cur; h_cur = h_nxt; h_nxt = tmp;
    }
    gemm_t<128,64,8,4,256><<<dim3(HH/64, BSs/128), 256>>>(
        p_enc, HH, glm_wref_w, HH, glm_wref_b, p_refg, HH);
    gemm_t<128,64,8,4,256><<<dim3(HH/64, BSs/128), 256>>>(
        p_enc, HH, ptr_wref_w, HH, ptr_wref_b, p_refp, HH);
    // decoder
    for (int k = 0; k < SS; k++){
        lstm_step<64,64,4,256><<<dim3(GG/64, BB/64), 256>>>(
            p_din, (long long)HH, p_wih_d, p_b1d,
            h_cur, p_whh_d, p_b2d,
            h_nxt, p_c, nullptr);
        float* tmp = h_cur; h_cur = h_nxt; h_nxt = tmp;
        gemm_t<32,64,4,4,128><<<dim3(HH/64, BB/32), 128>>>(
            h_cur, HH, glm_wq_w, HH, glm_wq_b, p_qw, HH);
        attn_kernel<<<BB, 256, ATTN_SMEM>>>(p_qw, glm_v_w, glm_v_b, p_refg, 0, k, out);
        gemm_t<32,64,4,4,128><<<dim3(HH/64, BB/32), 128>>>(
            p_q, HH, ptr_wq_w, HH, ptr_wq_b, p_qw, HH);
        attn_kernel<<<BB, 256, ATTN_SMEM>>>(p_qw, ptr_v_w, ptr_v_b, p_refp, 1, k, out);
    }
}

// round 16
// speedup vs baseline: 1.6365x; 1.2572x over previous
#include <cuda_runtime.h>
#include <stdint.h>
#include <math.h>

#define BB 1024
#define SS 100
#define HH 256
#define GG 1024            // 4*H
#define BSs (BB*SS)        // 102400
#define REF_PAD 257
#define ATTN_SMEM (SS*REF_PAD*4)

// ---------------- scratch ----------------
__device__ float g_embedded[(size_t)BSs*HH];
__device__ float g_enc_out[(size_t)BSs*HH];
__device__ float g_ref_g[(size_t)BSs*HH];
__device__ float g_ref_p[(size_t)BSs*HH];
__device__ float g_hA[BB*HH];
__device__ float g_hB[BB*HH];
__device__ float g_c[BB*HH];
__device__ float g_q[BB*HH];
__device__ float g_qw[BB*HH];
__device__ float g_dec_in[BB*HH];
__device__ unsigned char g_mask[BSs];
__device__ uint2 g_keys[SS];
// gate-interleaved weights/biases: row 4h+g <- row g*HH+h
__device__ float g_wih_e[GG*HH];
__device__ float g_whh_e[GG*HH];
__device__ float g_wih_d[GG*HH];
__device__ float g_whh_d[GG*HH];
__device__ float g_b1_e[GG];
__device__ float g_b2_e[GG];
__device__ float g_b1_d[GG];
__device__ float g_b2_d[GG];

// ---------------- XLA elemental tanh, FMA-contracted Horner ----------------
__device__ __forceinline__ float tanhx(float x){
    float xc = fminf(fmaxf(x, -9.0f), 9.0f);
    float x2 = __fmul_rn(xc, xc);
    float p = -2.76076847742355e-16f;
    p = fmaf(p, x2,  2.00018790482477e-13f);
    p = fmaf(p, x2, -8.60467152213735e-11f);
    p = fmaf(p, x2,  5.12229709037114e-08f);
    p = fmaf(p, x2,  1.48572235717979e-05f);
    p = fmaf(p, x2,  6.37261928875436e-04f);
    p = fmaf(p, x2,  4.89352455891786e-03f);
    float num = __fmul_rn(xc, p);
    float q = 1.19825839466702e-06f;
    q = fmaf(q, x2, 1.18534705686654e-04f);
    q = fmaf(q, x2, 2.26843463243900e-03f);
    q = fmaf(q, x2, 4.89352518554385e-03f);
    float r = __fdiv_rn(num, q);
    return (fabsf(x) < 0.0004f) ? x : r;
}
__device__ __forceinline__ float sigx(float x){
    float t = tanhx(__fmul_rn(0.5f, x));
    return fmaf(0.5f, t, 0.5f);
}
__device__ __forceinline__ float expd(float x){ return (float)exp((double)x); }
__device__ __forceinline__ float logd(float x){ return (float)log((double)x); }

// ---------------- threefry2x32 ----------------
__device__ __forceinline__ uint32_t rotl32(uint32_t x, int d){ return (x<<d)|(x>>(32-d)); }
__device__ __forceinline__ void threefry2x32(uint32_t k0, uint32_t k1, uint32_t& x0, uint32_t& x1){
    uint32_t ks2 = k0 ^ k1 ^ 0x1BD11BDAu;
    x0 += k0; x1 += k1;
    #define TF_R4(a,b,c,d) \
        x0 += x1; x1 = rotl32(x1,a); x1 ^= x0; \
        x0 += x1; x1 = rotl32(x1,b); x1 ^= x0; \
        x0 += x1; x1 = rotl32(x1,c); x1 ^= x0; \
        x0 += x1; x1 = rotl32(x1,d); x1 ^= x0;
    TF_R4(13,15,26,6);  x0 += k1;  x1 += ks2 + 1u;
    TF_R4(17,29,16,24); x0 += ks2; x1 += k0  + 2u;
    TF_R4(13,15,26,6);  x0 += k0;  x1 += k1  + 3u;
    TF_R4(17,29,16,24); x0 += k1;  x1 += ks2 + 4u;
    TF_R4(13,15,26,6);  x0 += ks2; x1 += k0  + 5u;
    #undef TF_R4
}

__global__ void keys_kernel(){
    int t = threadIdx.x;
    if (t < SS){
        uint32_t x0 = 0u, x1 = (uint32_t)t;
        threefry2x32(0u, 42u, x0, x1);
        g_keys[t] = make_uint2(x0, x1);
    }
}

__global__ void init_kernel(const float* __restrict__ start){
    int i = blockIdx.x*blockDim.x + threadIdx.x;
    if (i < BB*HH){ g_hA[i]=0.f; g_c[i]=0.f; g_dec_in[i] = start[i & (HH-1)]; }
    if (i < BSs)    g_mask[i] = 0;
}

// permute gate weights/biases: dst row 4h+g = src row g*HH+h
__global__ void prep_kernel(const float* __restrict__ ewih, const float* __restrict__ ewhh,
                            const float* __restrict__ ebi,  const float* __restrict__ ebh,
                            const float* __restrict__ dwih, const float* __restrict__ dwhh,
                            const float* __restrict__ dbi,  const float* __restrict__ dbh){
    int i = blockIdx.x*blockDim.x + threadIdx.x;
    int np = i >> 8;
    int k  = i & 255;
    int h  = np >> 2, g = np & 3;
    int src = ((g<<8) + h)*HH + k;
    g_wih_e[i] = ewih[src];
    g_whh_e[i] = ewhh[src];
    g_wih_d[i] = dwih[src];
    g_whh_d[i] = dwhh[src];
    if (i < GG){
        int nh = i >> 2, ng = i & 3;
        g_b1_e[i] = ebi[(ng<<8)+nh];  g_b2_e[i] = ebh[(ng<<8)+nh];
        g_b1_d[i] = dbi[(ng<<8)+nh];  g_b2_d[i] = dbh[(ng<<8)+nh];
    }
}

// embedded = inputs @ emb_w^T + emb_b
__global__ void embed_kernel(const float* __restrict__ inp, const float* __restrict__ w,
                             const float* __restrict__ bias){
    size_t i = (size_t)blockIdx.x*blockDim.x + threadIdx.x;
    int h = (int)(i & (HH-1));
    size_t bs = i >> 8;
    float acc = fmaf(inp[bs*2+1], w[h*2+1], __fmul_rn(inp[bs*2], w[h*2]));
    g_embedded[i] = __fadd_rn(acc, bias[h]);
}

// ---------------- generic GEMM (ref projections / qw) ----------------
template<int BM, int BN, int TM, int TN, int NT>
__global__ void __launch_bounds__(NT)
gemm_t(const float* __restrict__ A1, long long lda1,
       const float* __restrict__ W1, int K1, const float* __restrict__ bias1,
       float* __restrict__ C, int N){
    __shared__ float As[32][BM+4];
    __shared__ float Ws[32][BN+4];
    const int tid = threadIdx.x;
    const int txn = tid % (BN/TN);
    const int tym = tid / (BN/TN);
    const int n0 = blockIdx.x * BN, m0 = blockIdx.y * BM;
    float acc1[TM][TN];
    #pragma unroll
    for (int i = 0; i < TM; i++)
        #pragma unroll
        for (int j = 0; j < TN; j++) acc1[i][j] = 0.f;

    for (int kt = 0; kt < K1; kt += 32){
        #pragma unroll
        for (int i = tid; i < BM*32; i += NT){
            int k = i & 31, r = i >> 5;
            As[k][r] = A1[(size_t)(m0 + r)*lda1 + kt + k];
        }
        #pragma unroll
        for (int i = tid; i < BN*32; i += NT){
            int k = i & 31, r = i >> 5;
            Ws[k][r] = W1[(size_t)(n0 + r)*K1 + kt + k];
        }
        __syncthreads();
        #pragma unroll
        for (int kk = 0; kk < 32; kk++){
            float a[TM], w[TN];
            #pragma unroll
            for (int v = 0; v < TM/4; v++)
                *(float4*)(a + 4*v) = *(const float4*)(&As[kk][tym*TM + 4*v]);
            #pragma unroll
            for (int v = 0; v < TN/4; v++)
                *(float4*)(w + 4*v) = *(const float4*)(&Ws[kk][txn*TN + 4*v]);
            #pragma unroll
            for (int i = 0; i < TM; i++)
                #pragma unroll
                for (int j = 0; j < TN; j++)
                    acc1[i][j] = fmaf(a[i], w[j], acc1[i][j]);
        }
        __syncthreads();
    }
    #pragma unroll
    for (int i = 0; i < TM; i++){
        int r = m0 + tym*TM + i;
        #pragma unroll
        for (int jv = 0; jv < TN/4; jv++){
            float4 o; float* op = (float*)&o;
            #pragma unroll
            for (int u = 0; u < 4; u++){
                int n = n0 + txn*TN + jv*4 + u;
                op[u] = __fadd_rn(acc1[i][jv*4+u], bias1[n]);
            }
            *(float4*)(&C[(size_t)r*N + n0 + txn*TN + jv*4]) = o;
        }
    }
}

// ---------------- fused LSTM step: dual GEMM + cell epilogue ----------------
template<int BM, int BN, int TM, int NT>
__global__ void __launch_bounds__(NT)
lstm_step(const float* __restrict__ A1, long long lda1,
          const float* __restrict__ W1, const float* __restrict__ b1,
          const float* __restrict__ hprev, const float* __restrict__ W2,
          const float* __restrict__ b2,
          float* __restrict__ hnext, float* __restrict__ c,
          float* __restrict__ enc_slice){
    __shared__ float As[32][BM+4];
    __shared__ float Ws[32][BN+4];
    const int tid = threadIdx.x;
    const int txn = tid % (BN/4);
    const int tym = tid / (BN/4);
    const int n0 = blockIdx.x * BN, m0 = blockIdx.y * BM;
    float acc1[TM][4];
    float acc2[TM][4];
    #pragma unroll
    for (int i = 0; i < TM; i++)
        #pragma unroll
        for (int j = 0; j < 4; j++){ acc1[i][j] = 0.f; acc2[i][j] = 0.f; }

    for (int phase = 0; phase < 2; phase++){
        const float* A = (phase == 0) ? A1 : hprev;
        const float* W = (phase == 0) ? W1 : W2;
        long long lda = (phase == 0) ? lda1 : (long long)HH;
        for (int kt = 0; kt < HH; kt += 32){
            #pragma unroll
            for (int i = tid; i < BM*32; i += NT){
                int k = i & 31, r = i >> 5;
                As[k][r] = A[(size_t)(m0 + r)*lda + kt + k];
            }
            #pragma unroll
            for (int i = tid; i < BN*32; i += NT){
                int k = i & 31, r = i >> 5;
                Ws[k][r] = W[(size_t)(n0 + r)*HH + kt + k];
            }
            __syncthreads();
            #pragma unroll
            for (int kk = 0; kk < 32; kk++){
                float a[TM], w[4];
                #pragma unroll
                for (int v = 0; v < TM/4; v++)
                    *(float4*)(a + 4*v) = *(const float4*)(&As[kk][tym*TM + 4*v]);
                *(float4*)w = *(const float4*)(&Ws[kk][txn*4]);
                if (phase == 0){
                    #pragma unroll
                    for (int i = 0; i < TM; i++)
                        #pragma unroll
                        for (int j = 0; j < 4; j++)
                            acc1[i][j] = fmaf(a[i], w[j], acc1[i][j]);
                } else {
                    #pragma unroll
                    for (int i = 0; i < TM; i++)
                        #pragma unroll
                        for (int j = 0; j < 4; j++)
                            acc2[i][j] = fmaf(a[i], w[j], acc2[i][j]);
                }
            }
            __syncthreads();
        }
    }

    int n = n0 + txn*4;
    int hidx = n >> 2;
    float b1v[4] = { b1[n], b1[n+1], b1[n+2], b1[n+3] };
    float b2v[4] = { b2[n], b2[n+1], b2[n+2], b2[n+3] };
    #pragma unroll
    for (int i = 0; i < TM; i++){
        int r = m0 + tym*TM + i;
        float v[4];
        #pragma unroll
        for (int u = 0; u < 4; u++){
            float t = acc1[i][u];
            t = __fadd_rn(t, b1v[u]);
            t = __fadd_rn(t, acc2[i][u]);
            t = __fadd_rn(t, b2v[u]);
            v[u] = t;
        }
        float si = sigx(v[0]);
        float sf = sigx(v[1]);
        float tg = tanhx(v[2]);
        float so = sigx(v[3]);
        float cold = c[(size_t)r*HH + hidx];
        float cn = fmaf(sf, cold, __fmul_rn(si, tg));
        float hn = __fmul_rn(so, tanhx(cn));
        c[(size_t)r*HH + hidx] = cn;
        hnext[(size_t)r*HH + hidx] = hn;
        if (enc_slice) enc_slice[(size_t)r*SS*HH + hidx] = hn;
    }
}

// ---------------- attention: parallel tanh stage + exact sequential chain ------------
__global__ void __launch_bounds__(256)
attn_kernel(const float* __restrict__ qw_all, const float* __restrict__ vw,
            const float* __restrict__ vb, const float* __restrict__ refp,
            int do_sample, int step, float* __restrict__ out){
    extern __shared__ float sref[];                 // [SS][REF_PAD]
    int b = blockIdx.x, t = threadIdx.x;
    __shared__ float qs[HH], vs[HH];
    __shared__ float sl[SS], sp[SS], se[SS];
    __shared__ float rv[128];
    __shared__ int   ri[128];
    __shared__ float sstat[2];
    __shared__ int   schosen;

    qs[t] = qw_all[(size_t)b*HH + t];
    vs[t] = vw[t];

    const float* refb = refp + (size_t)b*SS*HH;
    const float4* ref4 = (const float4*)refb;
    #pragma unroll
    for (int i4 = t; i4 < SS*HH/4; i4 += 256){
        float4 v = ref4[i4];
        int flat = i4 * 4;
        int s = flat >> 8, h = flat & 255;
        float* d = sref + s*REF_PAD + h;
        d[0]=v.x; d[1]=v.y; d[2]=v.z; d[3]=v.w;
    }
    __syncthreads();

    // parallel elementwise tanh stage: u[s][h] = tanhx(ref[s][h] + q[h]), in-place.
    // iteration k: s=k, h=t -> addr k*257+t, banks (k+t)%32 conflict-free.
    #pragma unroll
    for (int k = 0; k < SS; k++){
        float* p = sref + k*REF_PAD + t;
        *p = tanhx(__fadd_rn(*p, qs[t]));
    }
    __syncthreads();

    const unsigned char* maskb = g_mask + (size_t)b*SS;

    // exact sequential fmaf chain over h ascending (bit-identical to reference order)
    if (t < SS){
        const float* r = sref + (size_t)t*REF_PAD;
        float acc = 0.f;
        #pragma unroll 8
        for (int h = 0; h < HH; h++)
            acc = fmaf(r[h], vs[h], acc);
        float tot = __fadd_rn(acc, vb[0]);
        float lg = maskb[t] ? -100000.0f : tot;
        sl[t] = __fmul_rn(10.0f, tanhx(lg));
    }
    __syncthreads();

    if (t < 128) rv[t] = (t < SS) ? sl[t] : -3.402823466e+38f;
    __syncthreads();
    for (int st = 64; st >= 1; st >>= 1){
        if (t < st) rv[t] = fmaxf(rv[t], rv[t+st]);
        __syncthreads();
    }
    float m = rv[0];
    __syncthreads();

    if (!do_sample){
        if (t < SS) se[t] = expd(__fsub_rn(sl[t], m));
        __syncthreads();
        if (t == 0){
            float ssum = 0.f;
            for (int s = 0; s < SS; s++) ssum = __fadd_rn(ssum, se[s]);
            sstat[1] = ssum;
        }
        __syncthreads();
        if (t < SS) sp[t] = __fdiv_rn(se[t], sstat[1]);
        __syncthreads();
        const float* encb = g_enc_out + (size_t)b*SS*HH;
        float acc = 0.f;
        for (int s = 0; s < SS; s++)
            acc = fmaf(sp[s], encb[(size_t)s*HH + t], acc);
        g_q[(size_t)b*HH + t] = acc;
    } else {
        if (t < SS){
            uint2 key = g_keys[step];
            uint32_t x0 = 0u, x1 = (uint32_t)(b*SS + t);
            threefry2x32(key.x, key.y, x0, x1);
            uint32_t bits = x0 ^ x1;
            float f = __uint_as_float((bits >> 9) | 0x3f800000u) - 1.0f;
            const float tiny = 1.1754943508222875e-38f;
            float u = fmaxf(tiny, __fadd_rn(f, tiny));
            float gmb = -logd(-logd(u));
            sp[t] = __fadd_rn(sl[t], gmb);
            se[t] = expd(__fsub_rn(sl[t], m));
        }
        __syncthreads();
        if (t < 128){
            rv[t] = (t < SS) ? sp[t] : -3.402823466e+38f;
            ri[t] = t;
        }
        __syncthreads();
        for (int st = 64; st >= 1; st >>= 1){
            if (t < st){
                float a = rv[t], bv = rv[t+st];
                int   ib = ri[t+st];
                if (bv > a || (bv == a && ib < ri[t])){ rv[t] = bv; ri[t] = ib; }
            }
            __syncthreads();
        }
        if (t == 0){
            int bi = ri[0];
            float ssum = 0.f;
            for (int s = 0; s < SS; s++) ssum = __fadd_rn(ssum, se[s]);
            float lse = logd(ssum);
            schosen = bi;
            float lp = __fsub_rn(__fsub_rn(sl[bi], m), lse);
            out[(size_t)b*SS + step] = lp;
            out[(size_t)BSs + (size_t)b*SS + step] = (float)bi;
            g_mask[(size_t)b*SS + bi] = 1;
        }
        __syncthreads();
        int ch = schosen;
        g_dec_in[(size_t)b*HH + t] = g_embedded[((size_t)b*SS + ch)*HH + t];
    }
}

// ---------------- host ----------------
extern "C" void kernel_launch(void* const* d_in, const int* in_sizes, int n_in,
                              void* d_out, int out_size){
    (void)in_sizes; (void)n_in; (void)out_size;
    const float* inputs    = (const float*)d_in[0];
    const float* emb_w     = (const float*)d_in[1];
    const float* emb_b     = (const float*)d_in[2];
    const float* enc_wih   = (const float*)d_in[3];
    const float* enc_whh   = (const float*)d_in[4];
    const float* enc_bih   = (const float*)d_in[5];
    const float* enc_bhh   = (const float*)d_in[6];
    const float* dec_wih   = (const float*)d_in[7];
    const float* dec_whh   = (const float*)d_in[8];
    const float* dec_bih   = (const float*)d_in[9];
    const float* dec_bhh   = (const float*)d_in[10];
    const float* ptr_wq_w  = (const float*)d_in[11];
    const float* ptr_wq_b  = (const float*)d_in[12];
    const float* ptr_wref_w= (const float*)d_in[13];
    const float* ptr_wref_b= (const float*)d_in[14];
    const float* ptr_v_w   = (const float*)d_in[15];
    const float* ptr_v_b   = (const float*)d_in[16];
    const float* glm_wq_w  = (const float*)d_in[17];
    const float* glm_wq_b  = (const float*)d_in[18];
    const float* glm_wref_w= (const float*)d_in[19];
    const float* glm_wref_b= (const float*)d_in[20];
    const float* glm_v_w   = (const float*)d_in[21];
    const float* glm_v_b   = (const float*)d_in[22];
    const float* start     = (const float*)d_in[23];
    float* out = (float*)d_out;

    float *p_emb, *p_enc, *p_refg, *p_refp, *p_hA, *p_hB, *p_c, *p_q, *p_qw, *p_din;
    float *p_wih_e, *p_whh_e, *p_wih_d, *p_whh_d, *p_b1e, *p_b2e, *p_b1d, *p_b2d;
    cudaGetSymbolAddress((void**)&p_emb,  g_embedded);
    cudaGetSymbolAddress((void**)&p_enc,  g_enc_out);
    cudaGetSymbolAddress((void**)&p_refg, g_ref_g);
    cudaGetSymbolAddress((void**)&p_refp, g_ref_p);
    cudaGetSymbolAddress((void**)&p_hA,   g_hA);
    cudaGetSymbolAddress((void**)&p_hB,   g_hB);
    cudaGetSymbolAddress((void**)&p_c,    g_c);
    cudaGetSymbolAddress((void**)&p_q,    g_q);
    cudaGetSymbolAddress((void**)&p_qw,   g_qw);
    cudaGetSymbolAddress((void**)&p_din,  g_dec_in);
    cudaGetSymbolAddress((void**)&p_wih_e, g_wih_e);
    cudaGetSymbolAddress((void**)&p_whh_e, g_whh_e);
    cudaGetSymbolAddress((void**)&p_wih_d, g_wih_d);
    cudaGetSymbolAddress((void**)&p_whh_d, g_whh_d);
    cudaGetSymbolAddress((void**)&p_b1e, g_b1_e);
    cudaGetSymbolAddress((void**)&p_b2e, g_b2_e);
    cudaGetSymbolAddress((void**)&p_b1d, g_b1_d);
    cudaGetSymbolAddress((void**)&p_b2d, g_b2_d);

    static int attr_done = 0;
    if (!attr_done){
        cudaFuncSetAttribute(attn_kernel, cudaFuncAttributeMaxDynamicSharedMemorySize,
                             ATTN_SMEM);
        attr_done = 1;
    }

    init_kernel<<<(BB*HH+255)/256, 256>>>(start);
    keys_kernel<<<1, 128>>>();
    prep_kernel<<<(GG*HH)/256, 256>>>(enc_wih, enc_whh, enc_bih, enc_bhh,
                                      dec_wih, dec_whh, dec_bih, dec_bhh);
    embed_kernel<<<(unsigned)(((size_t)BSs*HH)/256), 256>>>(inputs, emb_w, emb_b);

    float* h_cur = p_hA;
    float* h_nxt = p_hB;
    for (int s = 0; s < SS; s++){
        lstm_step<64,64,4,256><<<dim3(GG/64, BB/64), 256>>>(
            p_emb + (size_t)s*HH, (long long)SS*HH, p_wih_e, p_b1e,
            h_cur, p_whh_e, p_b2e,
            h_nxt, p_c, p_enc + (size_t)s*HH);
        float* tmp = h_cur; h_cur = h_nxt; h_nxt = tmp;
    }
    gemm_t<128,64,8,4,256><<<dim3(HH/64, BSs/128), 256>>>(
        p_enc, HH, glm_wref_w, HH, glm_wref_b, p_refg, HH);
    gemm_t<128,64,8,4,256><<<dim3(HH/64, BSs/128), 256>>>(
        p_enc, HH, ptr_wref_w, HH, ptr_wref_b, p_refp, HH);
    for (int k = 0; k < SS; k++){
        lstm_step<64,64,4,256><<<dim3(GG/64, BB/64), 256>>>(
            p_din, (long long)HH, p_wih_d, p_b1d,
            h_cur, p_whh_d, p_b2d,
            h_nxt, p_c, nullptr);
        float* tmp = h_cur; h_cur = h_nxt; h_nxt = tmp;
        gemm_t<32,64,4,4,128><<<dim3(HH/64, BB/32), 128>>>(
            h_cur, HH, glm_wq_w, HH, glm_wq_b, p_qw, HH);
        attn_kernel<<<BB, 256, ATTN_SMEM>>>(p_qw, glm_v_w, glm_v_b, p_refg, 0, k, out);
        gemm_t<32,64,4,4,128><<<dim3(HH/64, BB/32), 128>>>(
            p_q, HH, ptr_wq_w, HH, ptr_wq_b, p_qw, HH);
        attn_kernel<<<BB, 256, ATTN_SMEM>>>(p_qw, ptr_v_w, ptr_v_b, p_refp, 1, k, out);
    }
}